// round 10
// baseline (speedup 1.0000x reference)
#include <cuda_runtime.h>
#include <cuda_bf16.h>
#include <math.h>
#include <stdint.h>

#define NROWS 8192
#define TT    60
#define NCHUNK 128
#define NBLK  128

// -------- device scratch --------
// L0 hidden states as pre-swizzled hi/lo bf16 planes: [t][blk][plane(8KB)x2]
__device__ char  g_hs0p[(size_t)TT * NBLK * 16384];
__device__ float g_hlast[NROWS * 64];
__device__ float g_s1[NROWS];
__device__ float g_s2[NROWS];
__device__ float g_v1[64];
__device__ float g_v2[64];
__device__ float g_c12[2];
__device__ float g_s1sorted[NROWS];
__device__ int   g_sidx[NROWS];
__device__ float g_A[NROWS];
__device__ float g_B[NROWS];
__device__ float g_chunkA[NCHUNK * 65];
__device__ float g_chunkB[NCHUNK * 65];
__device__ float g_preB[(size_t)(NROWS + 1) * 65];
__device__ float g_suffA[(size_t)(NROWS + 1) * 65];

__device__ __forceinline__ float tanha(float x) {
    float r;
    asm("tanh.approx.f32 %0, %1;" : "=f"(r) : "f"(x));
    return r;
}
__device__ __forceinline__ float siga(float x) { return fmaf(tanha(0.5f * x), 0.5f, 0.5f); }

// -------- warp-MMA helpers (baseline sm_80+ ISA) --------
__device__ __forceinline__ uint32_t smem_u32(const void* p) {
    uint32_t a;
    asm("{ .reg .u64 t; cvta.to.shared.u64 t, %1; cvt.u32.u64 %0, t; }" : "=r"(a) : "l"(p));
    return a;
}
__device__ __forceinline__ void ldsm4(uint32_t* r, uint32_t a) {
    asm volatile("ldmatrix.sync.aligned.m8n8.x4.shared.b16 {%0,%1,%2,%3}, [%4];"
                 : "=r"(r[0]), "=r"(r[1]), "=r"(r[2]), "=r"(r[3]) : "r"(a));
}
__device__ __forceinline__ void ldsm4t(uint32_t* r, uint32_t a) {
    asm volatile("ldmatrix.sync.aligned.m8n8.x4.trans.shared.b16 {%0,%1,%2,%3}, [%4];"
                 : "=r"(r[0]), "=r"(r[1]), "=r"(r[2]), "=r"(r[3]) : "r"(a));
}
__device__ __forceinline__ void mma16816(float* d, const uint32_t* a, const uint32_t* b) {
    asm volatile(
        "mma.sync.aligned.m16n8k16.row.col.f32.bf16.bf16.f32 "
        "{%0,%1,%2,%3}, {%4,%5,%6,%7}, {%8,%9}, {%0,%1,%2,%3};"
        : "+f"(d[0]), "+f"(d[1]), "+f"(d[2]), "+f"(d[3])
        : "r"(a[0]), "r"(a[1]), "r"(a[2]), "r"(a[3]), "r"(b[0]), "r"(b[1]));
}
__device__ __forceinline__ uint32_t prmt(uint32_t a, uint32_t b, uint32_t s) {
    uint32_t r;
    asm("prmt.b32 %0, %1, %2, %3;" : "=r"(r) : "r"(a), "r"(b), "r"(s));
    return r;
}
__device__ __forceinline__ void bfsplit(float v, uint32_t& hi, uint32_t& lo) {
    __nv_bfloat16 h = __float2bfloat16(v);
    __nv_bfloat16 l = __float2bfloat16(v - __bfloat162float(h));
    hi = *(uint16_t*)&h;
    lo = *(uint16_t*)&l;
}
__device__ __forceinline__ uint16_t bf16hi(float v) {
    __nv_bfloat16 h = __float2bfloat16(v);
    return *(uint16_t*)&h;
}
// A tile [64 rows][128 k] bf16, 256B/row, swizzled 16B chunks
__device__ __forceinline__ uint32_t offA(int r, int k) {
    int ck = k >> 3;
    return (uint32_t)(r * 256 + (((ck & 8) | ((ck ^ r) & 7)) << 4) + (k & 7) * 2);
}
// W tile [k][256 n] bf16, 512B/row
__device__ __forceinline__ uint32_t offW(int k, int n) {
    int cn = n >> 3;
    return (uint32_t)(k * 512 + (((cn & 24) | ((cn ^ k) & 7)) << 4) + (n & 7) * 2);
}
// gmem h-plane: 64 rows x 64 j, 128B/row, same swizzle pattern as offA k<64
__device__ __forceinline__ uint32_t off8(int r, int j) {
    return (uint32_t)(r * 128 + ((((j >> 3) ^ r) & 7) << 4) + (j & 7) * 2);
}
__device__ __forceinline__ void cpasync16(uint32_t dst, const char* src) {
    asm volatile("cp.async.cg.shared.global [%0], [%1], 16;" :: "r"(dst), "l"(src) : "memory");
}

// =======================================================================
// HMMA LSTM v2: 128 blocks x 64 rows, 256 threads (8 warps).
// Warp wid owns ALL 64 rows x 32 cols (4 mtiles x 4 ntiles); B-hi frags
// for its cols are REGISTER-RESIDENT across all 60 steps (loaded once
// from gmem in mma frag layout). B-lo via ldsm from SMEM. A ping-pong,
// one __syncthreads per step. L1 x staged by raw cp.async from the
// pre-swizzled planes L0 wrote. 3-MMA bf16 split (bit-identical to R9).
// =======================================================================
template <int KW, int NCH, int FEAT, int LAYER>
__global__ void __launch_bounds__(256, 1)
lstm_mma(const float* __restrict__ xin, const float* __restrict__ Wih,
         const float* __restrict__ Whh, const float* __restrict__ bih,
         const float* __restrict__ bhh) {
    extern __shared__ char smem[];
    const int A0 = KW * 512;                 // W_LO occupies [0, KW*512)
    const int S_BIAS = A0 + 65536;           // two 32KB A buffers
    const uint32_t sbase = smem_u32(smem);

    const int tid = threadIdx.x, lane = tid & 31, wid = tid >> 5;
    const int t4 = lane & 3, g8 = lane >> 2;
    const int m = lane >> 3, q = lane & 7;
    const int rowb = blockIdx.x * 64;
    const int nb = wid * 32;                 // warp col base (8 warps x 32 = 256)

    auto wval = [&](int go, int k) -> float {
        return (k < 64) ? Whh[go * 64 + k]
                        : ((k - 64 < FEAT) ? Wih[go * FEAT + (k - 64)] : 0.f);
    };

    // ---- B-hi fragments into registers (once) ----
    uint32_t bhi[NCH][4][2];
    #pragma unroll
    for (int c = 0; c < NCH; ++c)
        #pragma unroll
        for (int nn = 0; nn < 4; ++nn) {
            int n = nb + nn * 8 + (lane >> 2);
            int go = (n & 3) * 64 + (n >> 2);
            int k0 = c * 16 + (lane & 3) * 2;
            bhi[c][nn][0] = (uint32_t)bf16hi(wval(go, k0)) |
                            ((uint32_t)bf16hi(wval(go, k0 + 1)) << 16);
            bhi[c][nn][1] = (uint32_t)bf16hi(wval(go, k0 + 8)) |
                            ((uint32_t)bf16hi(wval(go, k0 + 9)) << 16);
        }

    // ---- W_LO plane into SMEM ----
    for (int idx = tid; idx < KW * 256; idx += 256) {
        int k = idx >> 8, n = idx & 255;
        int go = (n & 3) * 64 + (n >> 2);
        float w = wval(go, k);
        __nv_bfloat16 h = __float2bfloat16(w);
        __nv_bfloat16 l = __float2bfloat16(w - __bfloat162float(h));
        *(uint16_t*)(smem + offW(k, n)) = *(uint16_t*)&l;
    }
    // zero both A buffers (64KB)
    for (int i = tid; i < 4096; i += 256) ((uint4*)(smem + A0))[i] = make_uint4(0, 0, 0, 0);
    if (tid < 256) {
        int go = (tid & 3) * 64 + (tid >> 2);
        ((float*)(smem + S_BIAS))[tid] = bih[go] + bhh[go];
    }
    __syncthreads();

    // ---- x staging helpers ----
    const int r0x = tid / 6, d0x = tid - r0x * 6;            // L0 elem 1
    const int r1x = (tid + 256) / 6, d1x = (tid + 256) - r1x * 6;  // L0 elem 2
    float xf0 = 0.f, xf1 = 0.f;

    auto pfx0 = [&](int t) {
        xf0 = xin[((size_t)(rowb + r0x) * TT + t) * 6 + d0x];
        if (tid < 128) xf1 = xin[((size_t)(rowb + r1x) * TT + t) * 6 + d1x];
    };
    auto stx0 = [&](int buf) {
        char* ah = smem + A0 + buf * 32768;
        uint32_t hi, lo;
        bfsplit(xf0, hi, lo);
        uint32_t o = offA(r0x, 64 + d0x);
        *(uint16_t*)(ah + o) = (uint16_t)hi;
        *(uint16_t*)(ah + 16384 + o) = (uint16_t)lo;
        if (tid < 128) {
            bfsplit(xf1, hi, lo);
            o = offA(r1x, 64 + d1x);
            *(uint16_t*)(ah + o) = (uint16_t)hi;
            *(uint16_t*)(ah + 16384 + o) = (uint16_t)lo;
        }
    };
    auto pfx_cp = [&](int t, int buf) {  // L1: raw 16B copies, pre-swizzled
        const char* gp = g_hs0p + ((size_t)t * NBLK + blockIdx.x) * 16384;
        #pragma unroll
        for (int i = 0; i < 4; ++i) {
            int idx = tid + i * 256;            // 0..1023
            int plane = idx >> 9, rc = idx & 511;
            int r = rc >> 3, cc = rc & 7;
            cpasync16(sbase + (uint32_t)(A0 + buf * 32768 + plane * 16384 +
                                         r * 256 + 128 + cc * 16),
                      gp + plane * 8192 + r * 128 + cc * 16);
        }
        asm volatile("cp.async.commit_group;" ::: "memory");
    };

    if (LAYER == 0) { pfx0(0); stx0(0); }
    else {
        pfx_cp(0, 0);
        asm volatile("cp.async.wait_group 0;" ::: "memory");
    }
    __syncthreads();

    float c[4][4];
    #pragma unroll
    for (int mt = 0; mt < 4; ++mt)
        #pragma unroll
        for (int nt = 0; nt < 4; ++nt) c[mt][nt] = 0.f;

    #pragma unroll 1
    for (int t = 0; t < TT; ++t) {
        const int p = t & 1;
        const uint32_t abase = sbase + (uint32_t)(A0 + p * 32768);
        char* anh = smem + A0 + (1 - p) * 32768;
        char* anl = anh + 16384;

        if (t < TT - 1) {
            if (LAYER == 0) pfx0(t + 1);
            else pfx_cp(t + 1, 1 - p);
        }

        // init accumulators from bias
        float d[4][4][4];
        #pragma unroll
        for (int nt = 0; nt < 4; ++nt) {
            float2 b2 = *(const float2*)(smem + S_BIAS + (nb + nt * 8 + t4 * 2) * 4);
            #pragma unroll
            for (int mt = 0; mt < 4; ++mt) {
                d[mt][nt][0] = b2.x; d[mt][nt][1] = b2.y;
                d[mt][nt][2] = b2.x; d[mt][nt][3] = b2.y;
            }
        }

        // ---- MMA phase ----
        #pragma unroll
        for (int ch = 0; ch < NCH; ++ch) {
            uint32_t ahi[4][4], alo[4][4], blo[8];
            #pragma unroll
            for (int mt = 0; mt < 4; ++mt) {
                uint32_t ao = offA(16 * mt + (m & 1) * 8 + q, ch * 16 + (m >> 1) * 8);
                ldsm4(ahi[mt], abase + ao);
                ldsm4(alo[mt], abase + 16384 + ao);
            }
            int bk = ch * 16 + (m & 1) * 8 + q;
            #pragma unroll
            for (int pp = 0; pp < 2; ++pp)
                ldsm4t(&blo[4 * pp], sbase + offW(bk, nb + (2 * pp + (m >> 1)) * 8));
            #pragma unroll
            for (int mt = 0; mt < 4; ++mt)
                #pragma unroll
                for (int nn = 0; nn < 4; ++nn) {
                    mma16816(d[mt][nn], ahi[mt], bhi[ch][nn]);
                    mma16816(d[mt][nn], alo[mt], bhi[ch][nn]);
                    mma16816(d[mt][nn], ahi[mt], &blo[2 * nn]);
                }
        }

        // ---- cell phase ----
        #pragma unroll
        for (int mt = 0; mt < 4; ++mt) {
            uint32_t w0a[4], w1a[4];
            float hf[4];
            #pragma unroll
            for (int nt = 0; nt < 4; ++nt) {
                float* dd = d[mt][nt];
                float e0 = __shfl_xor_sync(0xffffffffu, dd[0], 1);
                float e1 = __shfl_xor_sync(0xffffffffu, dd[1], 1);
                float e2 = __shfl_xor_sync(0xffffffffu, dd[2], 1);
                float e3 = __shfl_xor_sync(0xffffffffu, dd[3], 1);
                float iv, fv, gv, ov;
                if (t4 & 1) { iv = e2; fv = e3; gv = dd[2]; ov = dd[3]; }
                else        { iv = dd[0]; fv = dd[1]; gv = e0; ov = e1; }
                float cc = siga(fv) * c[mt][nt] + siga(iv) * tanha(gv);
                c[mt][nt] = cc;
                float hh = siga(ov) * tanha(cc);
                hf[nt] = hh;
                uint32_t hi, lo;
                bfsplit(hh, hi, lo);
                uint32_t hpk = hi | (lo << 16);
                uint32_t rv = __shfl_xor_sync(0xffffffffu, hpk, 2);
                w0a[nt] = (t4 & 2) ? rv : hpk;   // j even
                w1a[nt] = (t4 & 2) ? hpk : rv;   // j odd
            }
            const int row_mt = 16 * mt + g8 + ((t4 & 1) ? 8 : 0);
            const int ntb = (t4 & 2) ? 2 : 0;
            const int kb = wid * 8 + ((t4 & 2) ? 4 : 0);
            uint2 hiv = make_uint2(prmt(w0a[ntb], w1a[ntb], 0x5410),
                                   prmt(w0a[ntb + 1], w1a[ntb + 1], 0x5410));
            uint2 lov = make_uint2(prmt(w0a[ntb], w1a[ntb], 0x7632),
                                   prmt(w0a[ntb + 1], w1a[ntb + 1], 0x7632));
            if (t < TT - 1) {
                uint32_t o = offA(row_mt, kb);
                *(uint2*)(anh + o) = hiv;
                *(uint2*)(anl + o) = lov;
            }
            if (LAYER == 0) {
                char* gp = g_hs0p + ((size_t)t * NBLK + blockIdx.x) * 16384;
                uint32_t o = off8(row_mt, kb);
                *(uint2*)(gp + o) = hiv;
                *(uint2*)(gp + 8192 + o) = lov;
            } else if (t == TT - 1) {
                #pragma unroll
                for (int nt = 0; nt < 4; ++nt)
                    g_hlast[(rowb + row_mt) * 64 + wid * 8 + 2 * nt + (t4 >> 1)] = hf[nt];
            }
        }
        if (t < TT - 1) {
            if (LAYER == 0) stx0(1 - p);
            else asm volatile("cp.async.wait_group 0;" ::: "memory");
        }
        __syncthreads();
    }
}

// =======================================================================
// GAT prep + O(N) attention + head (passing versions, unchanged)
// =======================================================================
__global__ void prep1(const float* __restrict__ Wt, const float* __restrict__ bt,
                      const float* __restrict__ a) {
    int tid = threadIdx.x;
    if (tid < 64) {
        float v = 0.f;
        for (int g = 0; g < 64; ++g) v += Wt[g * 64 + tid] * a[g];
        g_v1[tid] = v;
    } else if (tid < 128) {
        int k = tid - 64;
        float v = 0.f;
        for (int g = 0; g < 64; ++g) v += Wt[g * 64 + k] * a[64 + g];
        g_v2[k] = v;
    }
    if (tid == 0) {
        float c = 0.f;
        for (int g = 0; g < 64; ++g) c += bt[g] * a[g];
        g_c12[0] = c;
    }
    if (tid == 1) {
        float c = 0.f;
        for (int g = 0; g < 64; ++g) c += bt[g] * a[64 + g];
        g_c12[1] = c;
    }
}

__global__ void prep2() {
    int lane = threadIdx.x & 31, w = threadIdx.x >> 5;
    int r = blockIdx.x * 8 + w;
    float l0 = g_hlast[r * 64 + lane], l1 = g_hlast[r * 64 + 32 + lane];
    float p1 = l0 * g_v1[lane] + l1 * g_v1[lane + 32];
    float p2 = l0 * g_v2[lane] + l1 * g_v2[lane + 32];
    #pragma unroll
    for (int o = 16; o; o >>= 1) {
        p1 += __shfl_xor_sync(0xffffffffu, p1, o);
        p2 += __shfl_xor_sync(0xffffffffu, p2, o);
    }
    if (lane == 0) {
        g_s1[r] = p1 + g_c12[0];
        g_s2[r] = p2 + g_c12[1];
    }
}

__global__ void __launch_bounds__(1024, 1) sort_kernel() {
    extern __shared__ char sraw[];
    float* k = (float*)sraw;
    int* v = (int*)(sraw + NROWS * 4);
    int tid = threadIdx.x;
    for (int i = tid; i < NROWS; i += 1024) { k[i] = g_s1[i]; v[i] = i; }
    for (int size = 2; size <= NROWS; size <<= 1) {
        for (int stride = size >> 1; stride > 0; stride >>= 1) {
            __syncthreads();
            #pragma unroll
            for (int e = 0; e < NROWS / 1024; ++e) {
                int i = e * 1024 + tid;
                int j = i ^ stride;
                if (j > i) {
                    bool up = ((i & size) == 0);
                    float ki = k[i], kj = k[j];
                    if ((ki > kj) == up) {
                        k[i] = kj; k[j] = ki;
                        int t = v[i]; v[i] = v[j]; v[j] = t;
                    }
                }
            }
        }
    }
    __syncthreads();
    for (int i = tid; i < NROWS; i += 1024) { g_s1sorted[i] = k[i]; g_sidx[i] = v[i]; }
}

__global__ void scan1() {
    __shared__ float sA[64], sB[64];
    __shared__ int sI[64];
    int c = blockIdx.x, tid = threadIdx.x;
    if (tid < 64) {
        float smax = g_s1sorted[NROWS - 1];
        float key = g_s1sorted[c * 64 + tid];
        float A = __expf(key - smax);
        float B = __expf(0.01f * (key - smax));
        sA[tid] = A; sB[tid] = B;
        sI[tid] = g_sidx[c * 64 + tid];
        g_A[c * 64 + tid] = A;
        g_B[c * 64 + tid] = B;
    }
    __syncthreads();
    if (tid <= 64) {
        float sa = 0.f, sb = 0.f;
        #pragma unroll 4
        for (int mq = 0; mq < 64; ++mq) {
            float xv = (tid < 64) ? g_hlast[sI[mq] * 64 + tid] : 1.f;
            sa += sA[mq] * xv;
            sb += sB[mq] * xv;
        }
        g_chunkA[c * 65 + tid] = sa;
        g_chunkB[c * 65 + tid] = sb;
    }
}

__global__ void scan2() {
    __shared__ float bufB[NCHUNK], bufA[NCHUNK];
    int d = blockIdx.x;
    int c = threadIdx.x;
    float origB = g_chunkB[c * 65 + d];
    float origA = g_chunkA[c * 65 + d];
    bufB[c] = origB;
    bufA[NCHUNK - 1 - c] = origA;
    __syncthreads();
    #pragma unroll
    for (int off = 1; off < NCHUNK; off <<= 1) {
        float tb = (c >= off) ? bufB[c - off] : 0.f;
        float ta = (c >= off) ? bufA[c - off] : 0.f;
        __syncthreads();
        bufB[c] += tb;
        bufA[c] += ta;
        __syncthreads();
    }
    g_chunkB[c * 65 + d] = bufB[c] - origB;
    g_chunkA[c * 65 + d] = bufA[NCHUNK - 1 - c] - origA;
}

__global__ void scan3() {
    __shared__ float sA[64], sB[64];
    __shared__ int sI[64];
    int c = blockIdx.x, tid = threadIdx.x;
    if (tid < 64) {
        sA[tid] = g_A[c * 64 + tid];
        sB[tid] = g_B[c * 64 + tid];
        sI[tid] = g_sidx[c * 64 + tid];
    }
    __syncthreads();
    if (tid <= 64) {
        int d = tid;
        float run = g_chunkB[c * 65 + d];
        #pragma unroll 4
        for (int mq = 0; mq < 64; ++mq) {
            size_t kk = (size_t)(c * 64 + mq);
            g_preB[kk * 65 + d] = run;
            float xv = (d < 64) ? g_hlast[sI[mq] * 64 + d] : 1.f;
            run += sB[mq] * xv;
        }
        if (c == NCHUNK - 1) g_preB[(size_t)NROWS * 65 + d] = run;
        float runA = g_chunkA[c * 65 + d];
        #pragma unroll 4
        for (int mq = 63; mq >= 0; --mq) {
            float xv = (d < 64) ? g_hlast[sI[mq] * 64 + d] : 1.f;
            runA += sA[mq] * xv;
            g_suffA[(size_t)(c * 64 + mq) * 65 + d] = runA;
        }
        if (c == NCHUNK - 1) g_suffA[(size_t)NROWS * 65 + d] = 0.f;
    }
}

__global__ void __launch_bounds__(256)
final_kernel(const float* __restrict__ Wfc, const float* __restrict__ bfc,
             const float* __restrict__ Wout, const float* __restrict__ bout,
             float* __restrict__ out) {
    __shared__ float sWfcT[64 * 65];
    __shared__ float sWo[64], sBfc[64];
    __shared__ float sZ[8][64];
    int tid = threadIdx.x;
    for (int idx = tid; idx < 4096; idx += 256) {
        int cc = idx >> 6, kq = idx & 63;
        sWfcT[kq * 65 + cc] = Wfc[idx];
    }
    if (tid < 64) { sWo[tid] = Wout[tid]; sBfc[tid] = bfc[tid]; }
    __syncthreads();

    int wy = tid >> 5, l = tid & 31;
    int i = blockIdx.x * 8 + wy;
    float smax = g_s1sorted[NROWS - 1];
    float s2 = g_s2[i];
    float thr = -s2;

    int kk = 0;
    #pragma unroll
    for (int st = 4096; st > 0; st >>= 1)
        if (kk + st <= NROWS && g_s1sorted[kk + st - 1] <= thr) kk += st;

    float u = s2 + smax;
    float fA, fB;
    if (u > 0.f) { fA = 1.f;               fB = __expf(-0.99f * u); }
    else         { fA = __expf(0.99f * u); fB = 1.f; }

    const float* suff = &g_suffA[(size_t)kk * 65];
    const float* pre  = &g_preB[(size_t)kk * 65];
    float inv = __fdividef(1.f, fA * suff[64] + fB * pre[64]);
    #pragma unroll
    for (int h = 0; h < 2; ++h) {
        int d = l + h * 32;
        sZ[wy][d] = (fA * suff[d] + fB * pre[d]) * inv + g_hlast[i * 64 + d];
    }
    __syncwarp();

    float yp = 0.f;
    #pragma unroll
    for (int h = 0; h < 2; ++h) {
        int c = l + h * 32;
        float dot = sBfc[c];
        #pragma unroll 16
        for (int kq = 0; kq < 64; ++kq) dot += sZ[wy][kq] * sWfcT[kq * 65 + c];
        dot = dot > 0.f ? dot : 0.01f * dot;
        yp += dot * sWo[c];
    }
    #pragma unroll
    for (int o = 16; o; o >>= 1) yp += __shfl_xor_sync(0xffffffffu, yp, o);
    if (l == 0) out[i] = yp + bout[0];
}

// =======================================================================
extern "C" void kernel_launch(void* const* d_in, const int* in_sizes, int n_in,
                              void* d_out, int out_size) {
    const float* x    = (const float*)d_in[0];
    const float* Wih0 = (const float*)d_in[1];
    const float* Whh0 = (const float*)d_in[2];
    const float* bih0 = (const float*)d_in[3];
    const float* bhh0 = (const float*)d_in[4];
    const float* Wih1 = (const float*)d_in[5];
    const float* Whh1 = (const float*)d_in[6];
    const float* bih1 = (const float*)d_in[7];
    const float* bhh1 = (const float*)d_in[8];
    const float* Wt   = (const float*)d_in[9];
    const float* bt   = (const float*)d_in[10];
    const float* a    = (const float*)d_in[11];
    const float* Wfc  = (const float*)d_in[12];
    const float* bfc  = (const float*)d_in[13];
    const float* Wout = (const float*)d_in[14];
    const float* bout = (const float*)d_in[15];
    float* out = (float*)d_out;

    const int SM_L0 = 80 * 512 + 65536 + 1024;    // 107520 B
    const int SM_L1 = 128 * 512 + 65536 + 1024;   // 132096 B
    const int SM_SORT = NROWS * 8;

    cudaFuncSetAttribute(lstm_mma<80, 5, 6, 0>, cudaFuncAttributeMaxDynamicSharedMemorySize, SM_L0);
    cudaFuncSetAttribute(lstm_mma<128, 8, 64, 1>, cudaFuncAttributeMaxDynamicSharedMemorySize, SM_L1);
    cudaFuncSetAttribute(sort_kernel, cudaFuncAttributeMaxDynamicSharedMemorySize, SM_SORT);

    lstm_mma<80, 5, 6, 0><<<NBLK, 256, SM_L0>>>(x, Wih0, Whh0, bih0, bhh0);
    lstm_mma<128, 8, 64, 1><<<NBLK, 256, SM_L1>>>(x, Wih1, Whh1, bih1, bhh1);
    prep1<<<1, 128>>>(Wt, bt, a);
    prep2<<<NROWS / 8, 256>>>();
    sort_kernel<<<1, 1024, SM_SORT>>>();
    scan1<<<NCHUNK, 128>>>();
    scan2<<<65, NCHUNK>>>();
    scan3<<<NCHUNK, 128>>>();
    final_kernel<<<NROWS / 8, 256>>>(Wfc, bfc, Wout, bout, out);
}

// round 11
// speedup vs baseline: 1.2301x; 1.2301x over previous
#include <cuda_runtime.h>
#include <cuda_fp16.h>
#include <math.h>
#include <stdint.h>

#define NROWS 8192
#define TT    60
#define NCHUNK 128
#define NBLK  128

// -------- device scratch --------
// L0 hidden states: pre-swizzled fp16 plane per (t, blk): 8KB
__device__ char  g_hs0p[(size_t)TT * NBLK * 8192];
__device__ float g_hlast[NROWS * 64];
__device__ float g_s1[NROWS];
__device__ float g_s2[NROWS];
__device__ float g_v1[64];
__device__ float g_v2[64];
__device__ float g_c12[2];
__device__ float g_s1sorted[NROWS];
__device__ int   g_sidx[NROWS];
__device__ float g_A[NROWS];
__device__ float g_B[NROWS];
__device__ float g_chunkA[NCHUNK * 65];
__device__ float g_chunkB[NCHUNK * 65];
__device__ float g_preB[(size_t)(NROWS + 1) * 65];
__device__ float g_suffA[(size_t)(NROWS + 1) * 65];

__device__ __forceinline__ float tanha(float x) {
    float r;
    asm("tanh.approx.f32 %0, %1;" : "=f"(r) : "f"(x));
    return r;
}
__device__ __forceinline__ float siga(float x) { return fmaf(tanha(0.5f * x), 0.5f, 0.5f); }

// -------- warp-MMA helpers --------
__device__ __forceinline__ uint32_t smem_u32(const void* p) {
    uint32_t a;
    asm("{ .reg .u64 t; cvta.to.shared.u64 t, %1; cvt.u32.u64 %0, t; }" : "=r"(a) : "l"(p));
    return a;
}
__device__ __forceinline__ void barg(int id) {
    asm volatile("bar.sync %0, 128;" :: "r"(id) : "memory");
}
__device__ __forceinline__ void ldsm4(uint32_t* r, uint32_t a) {
    asm volatile("ldmatrix.sync.aligned.m8n8.x4.shared.b16 {%0,%1,%2,%3}, [%4];"
                 : "=r"(r[0]), "=r"(r[1]), "=r"(r[2]), "=r"(r[3]) : "r"(a));
}
__device__ __forceinline__ void ldsm4t(uint32_t* r, uint32_t a) {
    asm volatile("ldmatrix.sync.aligned.m8n8.x4.trans.shared.b16 {%0,%1,%2,%3}, [%4];"
                 : "=r"(r[0]), "=r"(r[1]), "=r"(r[2]), "=r"(r[3]) : "r"(a));
}
__device__ __forceinline__ void mma16816(float* d, const uint32_t* a, const uint32_t* b) {
    asm volatile(
        "mma.sync.aligned.m16n8k16.row.col.f32.f16.f16.f32 "
        "{%0,%1,%2,%3}, {%4,%5,%6,%7}, {%8,%9}, {%0,%1,%2,%3};"
        : "+f"(d[0]), "+f"(d[1]), "+f"(d[2]), "+f"(d[3])
        : "r"(a[0]), "r"(a[1]), "r"(a[2]), "r"(a[3]), "r"(b[0]), "r"(b[1]));
}
__device__ __forceinline__ uint16_t f2h(float v) {
    __half h = __float2half_rn(v);
    return *(uint16_t*)&h;
}
__device__ __forceinline__ void cpasync16(uint32_t dst, const char* src) {
    asm volatile("cp.async.cg.shared.global [%0], [%1], 16;" :: "r"(dst), "l"(src) : "memory");
}
// A tile [64 rows][128 k] fp16, 256B/row, swizzled 16B chunks
__device__ __forceinline__ uint32_t offA(int r, int k) {
    int ck = k >> 3;
    return (uint32_t)(r * 256 + (((ck & 8) | ((ck ^ r) & 7)) << 4) + (k & 7) * 2);
}
// W tile [k][256 n] fp16, 512B/row
__device__ __forceinline__ uint32_t offW(int k, int n) {
    int cn = n >> 3;
    return (uint32_t)(k * 512 + (((cn & 24) | ((cn ^ k) & 7)) << 4) + (n & 7) * 2);
}
// gmem h-plane: 64 rows x 64 j fp16, 128B/row, swizzle matches offA k<64
__device__ __forceinline__ uint32_t off8(int r, int j) {
    return (uint32_t)(r * 128 + ((((j >> 3) ^ r) & 7) << 4) + (j & 7) * 2);
}

// =======================================================================
// HMMA LSTM v3 (fp16 2-MMA): 128 blocks x 64 rows, 512 threads (16 warps).
// rw = wid>>2 (row-group), cg = wid&3 (scheduler) -> per-SMSP drift.
// A (h|x) single fp16 plane, ping-pong; W split fp16 hi/lo in SMEM.
// 2 MMAs per chunk-tile: A*Whi + A*Wlo (W exact; only A quantized e5m10).
// One named barrier per step.
// =======================================================================
template <int KW, int NCH, int FEAT, int LAYER>
__global__ void __launch_bounds__(512, 1)
lstm_mma(const float* __restrict__ xin, const float* __restrict__ Wih,
         const float* __restrict__ Whh, const float* __restrict__ bih,
         const float* __restrict__ bhh) {
    extern __shared__ char smem[];
    const int W_HI = 0, W_LO = KW * 512;
    const int A0 = 2 * KW * 512;            // two 16KB A buffers
    const int S_BIAS = A0 + 32768;
    const uint32_t sbase = smem_u32(smem);

    const int tid = threadIdx.x, lane = tid & 31, wid = tid >> 5;
    const int rw = wid >> 2, cg = wid & 3;
    const int t4 = lane & 3, g8 = lane >> 2;
    const int r0 = rw * 16;
    const int rowb = blockIdx.x * 64;
    const int row_st = r0 + g8 + ((t4 & 1) ? 8 : 0);
    const int m = lane >> 3, q = lane & 7;
    const int t128 = cg * 32 + lane;        // index within row-group
    const int barid = rw + 1;

    // ---- stage W (permuted n=4j+type, split fp16 hi/lo) ----
    for (int idx = tid; idx < KW * 256; idx += 512) {
        int k = idx >> 8, n = idx & 255;
        int go = (n & 3) * 64 + (n >> 2);
        float w = (k < 64) ? Whh[go * 64 + k]
                           : ((k - 64 < FEAT) ? Wih[go * FEAT + (k - 64)] : 0.f);
        uint16_t hb = f2h(w);
        float hf_;
        {
            __half hh = *(__half*)&hb;
            hf_ = __half2float(hh);
        }
        uint16_t lb = f2h(w - hf_);
        uint32_t o = offW(k, n);
        *(uint16_t*)(smem + W_HI + o) = hb;
        *(uint16_t*)(smem + W_LO + o) = lb;
    }
    // zero both A buffers (32KB)
    for (int i = tid; i < 2048; i += 512) ((uint4*)(smem + A0))[i] = make_uint4(0, 0, 0, 0);
    if (tid < 256) {
        int go = (tid & 3) * 64 + (tid >> 2);
        ((float*)(smem + S_BIAS))[tid] = bih[go] + bhh[go];
    }
    __syncthreads();

    // group-local x staging (rows r0..r0+15 only)
    int xrow = 0, xd = 0;
    if (LAYER == 0) { xrow = r0 + t128 / 6; xd = t128 - (t128 / 6) * 6; }
    const int cprow = r0 + (t128 >> 3);     // L1: row for cp.async
    const int cpcc = t128 & 7;              // L1: 16B chunk within row
    float xf = 0.f;

    auto pfx0 = [&](int t) {
        if (t128 < 96) xf = xin[((size_t)(rowb + xrow) * TT + t) * 6 + xd];
    };
    auto stx0 = [&](int buf) {
        if (t128 < 96)
            *(uint16_t*)(smem + A0 + buf * 16384 + offA(xrow, 64 + xd)) = f2h(xf);
    };
    auto pfx_cp = [&](int t, int buf) {   // L1: one 16B cp.async per thread
        const char* gp = g_hs0p + ((size_t)t * NBLK + blockIdx.x) * 8192;
        cpasync16(sbase + (uint32_t)(A0 + buf * 16384 + cprow * 256 + 128 + cpcc * 16),
                  gp + cprow * 128 + cpcc * 16);
        asm volatile("cp.async.commit_group;" ::: "memory");
    };

    if (LAYER == 0) { pfx0(0); stx0(0); }
    else {
        pfx_cp(0, 0);
        asm volatile("cp.async.wait_group 0;" ::: "memory");
    }
    __syncthreads();

    float c[8];
    #pragma unroll
    for (int nt = 0; nt < 8; ++nt) c[nt] = 0.f;

    #pragma unroll 1
    for (int t = 0; t < TT; ++t) {
        const int p = t & 1;
        const uint32_t abase = sbase + (uint32_t)(A0 + p * 16384);
        char* an = smem + A0 + (1 - p) * 16384;   // next buffer

        if (t < TT - 1) {
            if (LAYER == 0) pfx0(t + 1);
            else pfx_cp(t + 1, 1 - p);
        }

        float d[8][4];
        #pragma unroll
        for (int nt = 0; nt < 8; ++nt) {
            float2 b2 = *(const float2*)(smem + S_BIAS + (cg * 64 + nt * 8 + t4 * 2) * 4);
            d[nt][0] = b2.x; d[nt][1] = b2.y; d[nt][2] = b2.x; d[nt][3] = b2.y;
        }

        // ---- MMA phase (2 MMAs per chunk-tile) ----
        #pragma unroll
        for (int ch = 0; ch < NCH; ++ch) {
            int ar = r0 + (m & 1) * 8 + q;
            int ak = ch * 16 + (m >> 1) * 8;
            uint32_t av[4];
            ldsm4(av, abase + offA(ar, ak));
            int bk = ch * 16 + (m & 1) * 8 + q;
            uint32_t bhi[16], blo[16];
            #pragma unroll
            for (int pp = 0; pp < 4; ++pp) {
                uint32_t bo = offW(bk, cg * 64 + (2 * pp + (m >> 1)) * 8);
                ldsm4t(&bhi[4 * pp], sbase + W_HI + bo);
                ldsm4t(&blo[4 * pp], sbase + W_LO + bo);
            }
            #pragma unroll
            for (int nt = 0; nt < 8; ++nt) mma16816(d[nt], av, &bhi[2 * nt]);
            #pragma unroll
            for (int nt = 0; nt < 8; ++nt) mma16816(d[nt], av, &blo[2 * nt]);
        }

        // ---- cell phase ----
        float hf[8];
        uint32_t w0a[8], w1a[8];
        #pragma unroll
        for (int nt = 0; nt < 8; ++nt) {
            float e0 = __shfl_xor_sync(0xffffffffu, d[nt][0], 1);
            float e1 = __shfl_xor_sync(0xffffffffu, d[nt][1], 1);
            float e2 = __shfl_xor_sync(0xffffffffu, d[nt][2], 1);
            float e3 = __shfl_xor_sync(0xffffffffu, d[nt][3], 1);
            float iv, fv, gv, ov;
            if (t4 & 1) { iv = e2; fv = e3; gv = d[nt][2]; ov = d[nt][3]; }
            else        { iv = d[nt][0]; fv = d[nt][1]; gv = e0; ov = e1; }
            float cc = siga(fv) * c[nt] + siga(iv) * tanha(gv);
            c[nt] = cc;
            float hh = siga(ov) * tanha(cc);
            hf[nt] = hh;
            uint32_t hpk = (uint32_t)f2h(hh);
            uint32_t rv = __shfl_xor_sync(0xffffffffu, hpk, 2);
            w0a[nt] = (t4 & 2) ? rv : hpk;   // j even
            w1a[nt] = (t4 & 2) ? hpk : rv;   // j odd
        }
        const int ntb = (t4 & 2) ? 4 : 0;
        const int kb = cg * 16 + ((t4 & 2) ? 8 : 0);
        uint4 pk = make_uint4(w0a[ntb] | (w1a[ntb] << 16),
                              w0a[ntb + 1] | (w1a[ntb + 1] << 16),
                              w0a[ntb + 2] | (w1a[ntb + 2] << 16),
                              w0a[ntb + 3] | (w1a[ntb + 3] << 16));
        if (t < TT - 1) *(uint4*)(an + offA(row_st, kb)) = pk;
        if (LAYER == 0) {
            char* gp = g_hs0p + ((size_t)t * NBLK + blockIdx.x) * 8192;
            *(uint4*)(gp + off8(row_st, kb)) = pk;
        } else if (t == TT - 1) {
            #pragma unroll
            for (int nt = 0; nt < 8; ++nt)
                g_hlast[(rowb + row_st) * 64 + cg * 16 + 2 * nt + (t4 >> 1)] = hf[nt];
        }
        if (t < TT - 1) {
            if (LAYER == 0) stx0(1 - p);
            else asm volatile("cp.async.wait_group 0;" ::: "memory");
        }
        barg(barid);  // group's stores -> next step's reads
    }
}

// =======================================================================
// GAT prep + O(N) attention + head (passing versions, unchanged)
// =======================================================================
__global__ void prep1(const float* __restrict__ Wt, const float* __restrict__ bt,
                      const float* __restrict__ a) {
    int tid = threadIdx.x;
    if (tid < 64) {
        float v = 0.f;
        for (int g = 0; g < 64; ++g) v += Wt[g * 64 + tid] * a[g];
        g_v1[tid] = v;
    } else if (tid < 128) {
        int k = tid - 64;
        float v = 0.f;
        for (int g = 0; g < 64; ++g) v += Wt[g * 64 + k] * a[64 + g];
        g_v2[k] = v;
    }
    if (tid == 0) {
        float c = 0.f;
        for (int g = 0; g < 64; ++g) c += bt[g] * a[g];
        g_c12[0] = c;
    }
    if (tid == 1) {
        float c = 0.f;
        for (int g = 0; g < 64; ++g) c += bt[g] * a[64 + g];
        g_c12[1] = c;
    }
}

__global__ void prep2() {
    int lane = threadIdx.x & 31, w = threadIdx.x >> 5;
    int r = blockIdx.x * 8 + w;
    float l0 = g_hlast[r * 64 + lane], l1 = g_hlast[r * 64 + 32 + lane];
    float p1 = l0 * g_v1[lane] + l1 * g_v1[lane + 32];
    float p2 = l0 * g_v2[lane] + l1 * g_v2[lane + 32];
    #pragma unroll
    for (int o = 16; o; o >>= 1) {
        p1 += __shfl_xor_sync(0xffffffffu, p1, o);
        p2 += __shfl_xor_sync(0xffffffffu, p2, o);
    }
    if (lane == 0) {
        g_s1[r] = p1 + g_c12[0];
        g_s2[r] = p2 + g_c12[1];
    }
}

__global__ void __launch_bounds__(1024, 1) sort_kernel() {
    extern __shared__ char sraw[];
    float* k = (float*)sraw;
    int* v = (int*)(sraw + NROWS * 4);
    int tid = threadIdx.x;
    for (int i = tid; i < NROWS; i += 1024) { k[i] = g_s1[i]; v[i] = i; }
    for (int size = 2; size <= NROWS; size <<= 1) {
        for (int stride = size >> 1; stride > 0; stride >>= 1) {
            __syncthreads();
            #pragma unroll
            for (int e = 0; e < NROWS / 1024; ++e) {
                int i = e * 1024 + tid;
                int j = i ^ stride;
                if (j > i) {
                    bool up = ((i & size) == 0);
                    float ki = k[i], kj = k[j];
                    if ((ki > kj) == up) {
                        k[i] = kj; k[j] = ki;
                        int t = v[i]; v[i] = v[j]; v[j] = t;
                    }
                }
            }
        }
    }
    __syncthreads();
    for (int i = tid; i < NROWS; i += 1024) { g_s1sorted[i] = k[i]; g_sidx[i] = v[i]; }
}

__global__ void scan1() {
    __shared__ float sA[64], sB[64];
    __shared__ int sI[64];
    int c = blockIdx.x, tid = threadIdx.x;
    if (tid < 64) {
        float smax = g_s1sorted[NROWS - 1];
        float key = g_s1sorted[c * 64 + tid];
        float A = __expf(key - smax);
        float B = __expf(0.01f * (key - smax));
        sA[tid] = A; sB[tid] = B;
        sI[tid] = g_sidx[c * 64 + tid];
        g_A[c * 64 + tid] = A;
        g_B[c * 64 + tid] = B;
    }
    __syncthreads();
    if (tid <= 64) {
        float sa = 0.f, sb = 0.f;
        #pragma unroll 4
        for (int mq = 0; mq < 64; ++mq) {
            float xv = (tid < 64) ? g_hlast[sI[mq] * 64 + tid] : 1.f;
            sa += sA[mq] * xv;
            sb += sB[mq] * xv;
        }
        g_chunkA[c * 65 + tid] = sa;
        g_chunkB[c * 65 + tid] = sb;
    }
}

__global__ void scan2() {
    __shared__ float bufB[NCHUNK], bufA[NCHUNK];
    int d = blockIdx.x;
    int c = threadIdx.x;
    float origB = g_chunkB[c * 65 + d];
    float origA = g_chunkA[c * 65 + d];
    bufB[c] = origB;
    bufA[NCHUNK - 1 - c] = origA;
    __syncthreads();
    #pragma unroll
    for (int off = 1; off < NCHUNK; off <<= 1) {
        float tb = (c >= off) ? bufB[c - off] : 0.f;
        float ta = (c >= off) ? bufA[c - off] : 0.f;
        __syncthreads();
        bufB[c] += tb;
        bufA[c] += ta;
        __syncthreads();
    }
    g_chunkB[c * 65 + d] = bufB[c] - origB;
    g_chunkA[c * 65 + d] = bufA[NCHUNK - 1 - c] - origA;
}

__global__ void scan3() {
    __shared__ float sA[64], sB[64];
    __shared__ int sI[64];
    int c = blockIdx.x, tid = threadIdx.x;
    if (tid < 64) {
        sA[tid] = g_A[c * 64 + tid];
        sB[tid] = g_B[c * 64 + tid];
        sI[tid] = g_sidx[c * 64 + tid];
    }
    __syncthreads();
    if (tid <= 64) {
        int d = tid;
        float run = g_chunkB[c * 65 + d];
        #pragma unroll 4
        for (int mq = 0; mq < 64; ++mq) {
            size_t kk = (size_t)(c * 64 + mq);
            g_preB[kk * 65 + d] = run;
            float xv = (d < 64) ? g_hlast[sI[mq] * 64 + d] : 1.f;
            run += sB[mq] * xv;
        }
        if (c == NCHUNK - 1) g_preB[(size_t)NROWS * 65 + d] = run;
        float runA = g_chunkA[c * 65 + d];
        #pragma unroll 4
        for (int mq = 63; mq >= 0; --mq) {
            float xv = (d < 64) ? g_hlast[sI[mq] * 64 + d] : 1.f;
            runA += sA[mq] * xv;
            g_suffA[(size_t)(c * 64 + mq) * 65 + d] = runA;
        }
        if (c == NCHUNK - 1) g_suffA[(size_t)NROWS * 65 + d] = 0.f;
    }
}

__global__ void __launch_bounds__(256)
final_kernel(const float* __restrict__ Wfc, const float* __restrict__ bfc,
             const float* __restrict__ Wout, const float* __restrict__ bout,
             float* __restrict__ out) {
    __shared__ float sWfcT[64 * 65];
    __shared__ float sWo[64], sBfc[64];
    __shared__ float sZ[8][64];
    int tid = threadIdx.x;
    for (int idx = tid; idx < 4096; idx += 256) {
        int cc = idx >> 6, kq = idx & 63;
        sWfcT[kq * 65 + cc] = Wfc[idx];
    }
    if (tid < 64) { sWo[tid] = Wout[tid]; sBfc[tid] = bfc[tid]; }
    __syncthreads();

    int wy = tid >> 5, l = tid & 31;
    int i = blockIdx.x * 8 + wy;
    float smax = g_s1sorted[NROWS - 1];
    float s2 = g_s2[i];
    float thr = -s2;

    int kk = 0;
    #pragma unroll
    for (int st = 4096; st > 0; st >>= 1)
        if (kk + st <= NROWS && g_s1sorted[kk + st - 1] <= thr) kk += st;

    float u = s2 + smax;
    float fA, fB;
    if (u > 0.f) { fA = 1.f;               fB = __expf(-0.99f * u); }
    else         { fA = __expf(0.99f * u); fB = 1.f; }

    const float* suff = &g_suffA[(size_t)kk * 65];
    const float* pre  = &g_preB[(size_t)kk * 65];
    float inv = __fdividef(1.f, fA * suff[64] + fB * pre[64]);
    #pragma unroll
    for (int h = 0; h < 2; ++h) {
        int d = l + h * 32;
        sZ[wy][d] = (fA * suff[d] + fB * pre[d]) * inv + g_hlast[i * 64 + d];
    }
    __syncwarp();

    float yp = 0.f;
    #pragma unroll
    for (int h = 0; h < 2; ++h) {
        int c = l + h * 32;
        float dot = sBfc[c];
        #pragma unroll 16
        for (int kq = 0; kq < 64; ++kq) dot += sZ[wy][kq] * sWfcT[kq * 65 + c];
        dot = dot > 0.f ? dot : 0.01f * dot;
        yp += dot * sWo[c];
    }
    #pragma unroll
    for (int o = 16; o; o >>= 1) yp += __shfl_xor_sync(0xffffffffu, yp, o);
    if (l == 0) out[i] = yp + bout[0];
}

// =======================================================================
extern "C" void kernel_launch(void* const* d_in, const int* in_sizes, int n_in,
                              void* d_out, int out_size) {
    const float* x    = (const float*)d_in[0];
    const float* Wih0 = (const float*)d_in[1];
    const float* Whh0 = (const float*)d_in[2];
    const float* bih0 = (const float*)d_in[3];
    const float* bhh0 = (const float*)d_in[4];
    const float* Wih1 = (const float*)d_in[5];
    const float* Whh1 = (const float*)d_in[6];
    const float* bih1 = (const float*)d_in[7];
    const float* bhh1 = (const float*)d_in[8];
    const float* Wt   = (const float*)d_in[9];
    const float* bt   = (const float*)d_in[10];
    const float* a    = (const float*)d_in[11];
    const float* Wfc  = (const float*)d_in[12];
    const float* bfc  = (const float*)d_in[13];
    const float* Wout = (const float*)d_in[14];
    const float* bout = (const float*)d_in[15];
    float* out = (float*)d_out;

    const int SM_L0 = 2 * 80 * 512 + 32768 + 1024;    // 115712 B
    const int SM_L1 = 2 * 128 * 512 + 32768 + 1024;   // 164864 B
    const int SM_SORT = NROWS * 8;

    cudaFuncSetAttribute(lstm_mma<80, 5, 6, 0>, cudaFuncAttributeMaxDynamicSharedMemorySize, SM_L0);
    cudaFuncSetAttribute(lstm_mma<128, 8, 64, 1>, cudaFuncAttributeMaxDynamicSharedMemorySize, SM_L1);
    cudaFuncSetAttribute(sort_kernel, cudaFuncAttributeMaxDynamicSharedMemorySize, SM_SORT);

    lstm_mma<80, 5, 6, 0><<<NBLK, 512, SM_L0>>>(x, Wih0, Whh0, bih0, bhh0);
    lstm_mma<128, 8, 64, 1><<<NBLK, 512, SM_L1>>>(x, Wih1, Whh1, bih1, bhh1);
    prep1<<<1, 128>>>(Wt, bt, a);
    prep2<<<NROWS / 8, 256>>>();
    sort_kernel<<<1, 1024, SM_SORT>>>();
    scan1<<<NCHUNK, 128>>>();
    scan2<<<65, NCHUNK>>>();
    scan3<<<NCHUNK, 128>>>();
    final_kernel<<<NROWS / 8, 256>>>(Wfc, bfc, Wout, bout, out);
}

// round 12
// speedup vs baseline: 1.5284x; 1.2425x over previous
#include <cuda_runtime.h>
#include <cuda_fp16.h>
#include <math.h>
#include <stdint.h>

#define NROWS 8192
#define TT    60
#define NCHUNK 128
#define NBLK  128

// -------- device scratch --------
// L0 hidden states: pre-swizzled fp16 plane per (t, blk): 8KB
__device__ char  g_hs0p[(size_t)TT * NBLK * 8192];
__device__ float g_hlast[NROWS * 64];
__device__ float g_s1[NROWS];
__device__ float g_s2[NROWS];
__device__ float g_v1[64];
__device__ float g_v2[64];
__device__ float g_c12[2];
__device__ float g_s1sorted[NROWS];
__device__ int   g_sidx[NROWS];
__device__ float g_A[NROWS];
__device__ float g_B[NROWS];
__device__ float g_chunkA[NCHUNK * 65];
__device__ float g_chunkB[NCHUNK * 65];
__device__ float g_preB[(size_t)(NROWS + 1) * 65];
__device__ float g_suffA[(size_t)(NROWS + 1) * 65];

__device__ __forceinline__ float tanha(float x) {
    float r;
    asm("tanh.approx.f32 %0, %1;" : "=f"(r) : "f"(x));
    return r;
}
__device__ __forceinline__ float siga(float x) { return fmaf(tanha(0.5f * x), 0.5f, 0.5f); }

// -------- warp-MMA helpers --------
__device__ __forceinline__ uint32_t smem_u32(const void* p) {
    uint32_t a;
    asm("{ .reg .u64 t; cvta.to.shared.u64 t, %1; cvt.u32.u64 %0, t; }" : "=r"(a) : "l"(p));
    return a;
}
__device__ __forceinline__ void barg(int id) {
    asm volatile("bar.sync %0, 128;" :: "r"(id) : "memory");
}
__device__ __forceinline__ void ldsm4(uint32_t* r, uint32_t a) {
    asm volatile("ldmatrix.sync.aligned.m8n8.x4.shared.b16 {%0,%1,%2,%3}, [%4];"
                 : "=r"(r[0]), "=r"(r[1]), "=r"(r[2]), "=r"(r[3]) : "r"(a));
}
__device__ __forceinline__ void ldsm4t(uint32_t* r, uint32_t a) {
    asm volatile("ldmatrix.sync.aligned.m8n8.x4.trans.shared.b16 {%0,%1,%2,%3}, [%4];"
                 : "=r"(r[0]), "=r"(r[1]), "=r"(r[2]), "=r"(r[3]) : "r"(a));
}
__device__ __forceinline__ void mma16816(float* d, const uint32_t* a, const uint32_t* b) {
    asm volatile(
        "mma.sync.aligned.m16n8k16.row.col.f32.f16.f16.f32 "
        "{%0,%1,%2,%3}, {%4,%5,%6,%7}, {%8,%9}, {%0,%1,%2,%3};"
        : "+f"(d[0]), "+f"(d[1]), "+f"(d[2]), "+f"(d[3])
        : "r"(a[0]), "r"(a[1]), "r"(a[2]), "r"(a[3]), "r"(b[0]), "r"(b[1]));
}
__device__ __forceinline__ uint16_t f2h(float v) {
    __half h = __float2half_rn(v);
    return *(uint16_t*)&h;
}
__device__ __forceinline__ void cpasync16(uint32_t dst, const char* src) {
    asm volatile("cp.async.cg.shared.global [%0], [%1], 16;" :: "r"(dst), "l"(src) : "memory");
}
// A tile [64 rows][128 k] fp16, 256B/row, swizzled 16B chunks
__device__ __forceinline__ uint32_t offA(int r, int k) {
    int ck = k >> 3;
    return (uint32_t)(r * 256 + (((ck & 8) | ((ck ^ r) & 7)) << 4) + (k & 7) * 2);
}
// W tile [k][256 n] fp16, 512B/row
__device__ __forceinline__ uint32_t offW(int k, int n) {
    int cn = n >> 3;
    return (uint32_t)(k * 512 + (((cn & 24) | ((cn ^ k) & 7)) << 4) + (n & 7) * 2);
}
// gmem h-plane: 64 rows x 64 j fp16, 128B/row, swizzle matches offA k<64
__device__ __forceinline__ uint32_t off8(int r, int j) {
    return (uint32_t)(r * 128 + ((((j >> 3) ^ r) & 7) << 4) + (j & 7) * 2);
}

// =======================================================================
// HMMA LSTM v4 (fp16 single-MMA): 128 blocks x 64 rows, 512 threads.
// rw = wid>>2 (row-group), cg = wid&3 (scheduler) -> per-SMSP drift.
// A (h|x) single fp16 plane, ping-pong; W single fp16 plane in SMEM.
// 1 MMA per chunk-tile. One named barrier per step.
// =======================================================================
template <int KW, int NCH, int FEAT, int LAYER>
__global__ void __launch_bounds__(512, 1)
lstm_mma(const float* __restrict__ xin, const float* __restrict__ Wih,
         const float* __restrict__ Whh, const float* __restrict__ bih,
         const float* __restrict__ bhh) {
    extern __shared__ char smem[];
    const int A0 = KW * 512;                // W occupies [0, KW*512)
    const int S_BIAS = A0 + 32768;          // two 16KB A buffers
    const uint32_t sbase = smem_u32(smem);

    const int tid = threadIdx.x, lane = tid & 31, wid = tid >> 5;
    const int rw = wid >> 2, cg = wid & 3;
    const int t4 = lane & 3, g8 = lane >> 2;
    const int r0 = rw * 16;
    const int rowb = blockIdx.x * 64;
    const int row_st = r0 + g8 + ((t4 & 1) ? 8 : 0);
    const int m = lane >> 3, q = lane & 7;
    const int t128 = cg * 32 + lane;        // index within row-group
    const int barid = rw + 1;

    // ---- stage W (permuted n=4j+type, single fp16) ----
    for (int idx = tid; idx < KW * 256; idx += 512) {
        int k = idx >> 8, n = idx & 255;
        int go = (n & 3) * 64 + (n >> 2);
        float w = (k < 64) ? Whh[go * 64 + k]
                           : ((k - 64 < FEAT) ? Wih[go * FEAT + (k - 64)] : 0.f);
        *(uint16_t*)(smem + offW(k, n)) = f2h(w);
    }
    // zero both A buffers (32KB)
    for (int i = tid; i < 2048; i += 512) ((uint4*)(smem + A0))[i] = make_uint4(0, 0, 0, 0);
    if (tid < 256) {
        int go = (tid & 3) * 64 + (tid >> 2);
        ((float*)(smem + S_BIAS))[tid] = bih[go] + bhh[go];
    }
    __syncthreads();

    // group-local x staging (rows r0..r0+15 only)
    int xrow = 0, xd = 0;
    if (LAYER == 0) { xrow = r0 + t128 / 6; xd = t128 - (t128 / 6) * 6; }
    const int cprow = r0 + (t128 >> 3);     // L1: row for cp.async
    const int cpcc = t128 & 7;              // L1: 16B chunk within row
    float xf = 0.f;

    auto pfx0 = [&](int t) {
        if (t128 < 96) xf = xin[((size_t)(rowb + xrow) * TT + t) * 6 + xd];
    };
    auto stx0 = [&](int buf) {
        if (t128 < 96)
            *(uint16_t*)(smem + A0 + buf * 16384 + offA(xrow, 64 + xd)) = f2h(xf);
    };
    auto pfx_cp = [&](int t, int buf) {   // L1: one 16B cp.async per thread
        const char* gp = g_hs0p + ((size_t)t * NBLK + blockIdx.x) * 8192;
        cpasync16(sbase + (uint32_t)(A0 + buf * 16384 + cprow * 256 + 128 + cpcc * 16),
                  gp + cprow * 128 + cpcc * 16);
        asm volatile("cp.async.commit_group;" ::: "memory");
    };

    if (LAYER == 0) { pfx0(0); stx0(0); }
    else {
        pfx_cp(0, 0);
        asm volatile("cp.async.wait_group 0;" ::: "memory");
    }
    __syncthreads();

    float c[8];
    #pragma unroll
    for (int nt = 0; nt < 8; ++nt) c[nt] = 0.f;

    #pragma unroll 1
    for (int t = 0; t < TT; ++t) {
        const int p = t & 1;
        const uint32_t abase = sbase + (uint32_t)(A0 + p * 16384);
        char* an = smem + A0 + (1 - p) * 16384;   // next buffer

        if (t < TT - 1) {
            if (LAYER == 0) pfx0(t + 1);
            else pfx_cp(t + 1, 1 - p);
        }

        float d[8][4];
        #pragma unroll
        for (int nt = 0; nt < 8; ++nt) {
            float2 b2 = *(const float2*)(smem + S_BIAS + (cg * 64 + nt * 8 + t4 * 2) * 4);
            d[nt][0] = b2.x; d[nt][1] = b2.y; d[nt][2] = b2.x; d[nt][3] = b2.y;
        }

        // ---- MMA phase (1 MMA per chunk-tile) ----
        #pragma unroll
        for (int ch = 0; ch < NCH; ++ch) {
            int ar = r0 + (m & 1) * 8 + q;
            int ak = ch * 16 + (m >> 1) * 8;
            uint32_t av[4];
            ldsm4(av, abase + offA(ar, ak));
            int bk = ch * 16 + (m & 1) * 8 + q;
            uint32_t bw[16];
            #pragma unroll
            for (int pp = 0; pp < 4; ++pp)
                ldsm4t(&bw[4 * pp], sbase + offW(bk, cg * 64 + (2 * pp + (m >> 1)) * 8));
            #pragma unroll
            for (int nt = 0; nt < 8; ++nt) mma16816(d[nt], av, &bw[2 * nt]);
        }

        // ---- cell phase ----
        float hf[8];
        uint32_t w0a[8], w1a[8];
        #pragma unroll
        for (int nt = 0; nt < 8; ++nt) {
            float e0 = __shfl_xor_sync(0xffffffffu, d[nt][0], 1);
            float e1 = __shfl_xor_sync(0xffffffffu, d[nt][1], 1);
            float e2 = __shfl_xor_sync(0xffffffffu, d[nt][2], 1);
            float e3 = __shfl_xor_sync(0xffffffffu, d[nt][3], 1);
            float iv, fv, gv, ov;
            if (t4 & 1) { iv = e2; fv = e3; gv = d[nt][2]; ov = d[nt][3]; }
            else        { iv = d[nt][0]; fv = d[nt][1]; gv = e0; ov = e1; }
            float cc = siga(fv) * c[nt] + siga(iv) * tanha(gv);
            c[nt] = cc;
            float hh = siga(ov) * tanha(cc);
            hf[nt] = hh;
            uint32_t hpk = (uint32_t)f2h(hh);
            uint32_t rv = __shfl_xor_sync(0xffffffffu, hpk, 2);
            w0a[nt] = (t4 & 2) ? rv : hpk;   // j even
            w1a[nt] = (t4 & 2) ? hpk : rv;   // j odd
        }
        const int ntb = (t4 & 2) ? 4 : 0;
        const int kb = cg * 16 + ((t4 & 2) ? 8 : 0);
        uint4 pk = make_uint4(w0a[ntb] | (w1a[ntb] << 16),
                              w0a[ntb + 1] | (w1a[ntb + 1] << 16),
                              w0a[ntb + 2] | (w1a[ntb + 2] << 16),
                              w0a[ntb + 3] | (w1a[ntb + 3] << 16));
        if (t < TT - 1) *(uint4*)(an + offA(row_st, kb)) = pk;
        if (LAYER == 0) {
            char* gp = g_hs0p + ((size_t)t * NBLK + blockIdx.x) * 8192;
            *(uint4*)(gp + off8(row_st, kb)) = pk;
        } else if (t == TT - 1) {
            #pragma unroll
            for (int nt = 0; nt < 8; ++nt)
                g_hlast[(rowb + row_st) * 64 + cg * 16 + 2 * nt + (t4 >> 1)] = hf[nt];
        }
        if (t < TT - 1) {
            if (LAYER == 0) stx0(1 - p);
            else asm volatile("cp.async.wait_group 0;" ::: "memory");
        }
        barg(barid);  // group's stores -> next step's reads
    }
}

// =======================================================================
// GAT prep + O(N) attention + head (passing versions, unchanged)
// =======================================================================
__global__ void prep1(const float* __restrict__ Wt, const float* __restrict__ bt,
                      const float* __restrict__ a) {
    int tid = threadIdx.x;
    if (tid < 64) {
        float v = 0.f;
        for (int g = 0; g < 64; ++g) v += Wt[g * 64 + tid] * a[g];
        g_v1[tid] = v;
    } else if (tid < 128) {
        int k = tid - 64;
        float v = 0.f;
        for (int g = 0; g < 64; ++g) v += Wt[g * 64 + k] * a[64 + g];
        g_v2[k] = v;
    }
    if (tid == 0) {
        float c = 0.f;
        for (int g = 0; g < 64; ++g) c += bt[g] * a[g];
        g_c12[0] = c;
    }
    if (tid == 1) {
        float c = 0.f;
        for (int g = 0; g < 64; ++g) c += bt[g] * a[64 + g];
        g_c12[1] = c;
    }
}

__global__ void prep2() {
    int lane = threadIdx.x & 31, w = threadIdx.x >> 5;
    int r = blockIdx.x * 8 + w;
    float l0 = g_hlast[r * 64 + lane], l1 = g_hlast[r * 64 + 32 + lane];
    float p1 = l0 * g_v1[lane] + l1 * g_v1[lane + 32];
    float p2 = l0 * g_v2[lane] + l1 * g_v2[lane + 32];
    #pragma unroll
    for (int o = 16; o; o >>= 1) {
        p1 += __shfl_xor_sync(0xffffffffu, p1, o);
        p2 += __shfl_xor_sync(0xffffffffu, p2, o);
    }
    if (lane == 0) {
        g_s1[r] = p1 + g_c12[0];
        g_s2[r] = p2 + g_c12[1];
    }
}

__global__ void __launch_bounds__(1024, 1) sort_kernel() {
    extern __shared__ char sraw[];
    float* k = (float*)sraw;
    int* v = (int*)(sraw + NROWS * 4);
    int tid = threadIdx.x;
    for (int i = tid; i < NROWS; i += 1024) { k[i] = g_s1[i]; v[i] = i; }
    for (int size = 2; size <= NROWS; size <<= 1) {
        for (int stride = size >> 1; stride > 0; stride >>= 1) {
            __syncthreads();
            #pragma unroll
            for (int e = 0; e < NROWS / 1024; ++e) {
                int i = e * 1024 + tid;
                int j = i ^ stride;
                if (j > i) {
                    bool up = ((i & size) == 0);
                    float ki = k[i], kj = k[j];
                    if ((ki > kj) == up) {
                        k[i] = kj; k[j] = ki;
                        int t = v[i]; v[i] = v[j]; v[j] = t;
                    }
                }
            }
        }
    }
    __syncthreads();
    for (int i = tid; i < NROWS; i += 1024) { g_s1sorted[i] = k[i]; g_sidx[i] = v[i]; }
}

__global__ void scan1() {
    __shared__ float sA[64], sB[64];
    __shared__ int sI[64];
    int c = blockIdx.x, tid = threadIdx.x;
    if (tid < 64) {
        float smax = g_s1sorted[NROWS - 1];
        float key = g_s1sorted[c * 64 + tid];
        float A = __expf(key - smax);
        float B = __expf(0.01f * (key - smax));
        sA[tid] = A; sB[tid] = B;
        sI[tid] = g_sidx[c * 64 + tid];
        g_A[c * 64 + tid] = A;
        g_B[c * 64 + tid] = B;
    }
    __syncthreads();
    if (tid <= 64) {
        float sa = 0.f, sb = 0.f;
        #pragma unroll 4
        for (int mq = 0; mq < 64; ++mq) {
            float xv = (tid < 64) ? g_hlast[sI[mq] * 64 + tid] : 1.f;
            sa += sA[mq] * xv;
            sb += sB[mq] * xv;
        }
        g_chunkA[c * 65 + tid] = sa;
        g_chunkB[c * 65 + tid] = sb;
    }
}

__global__ void scan2() {
    __shared__ float bufB[NCHUNK], bufA[NCHUNK];
    int d = blockIdx.x;
    int c = threadIdx.x;
    float origB = g_chunkB[c * 65 + d];
    float origA = g_chunkA[c * 65 + d];
    bufB[c] = origB;
    bufA[NCHUNK - 1 - c] = origA;
    __syncthreads();
    #pragma unroll
    for (int off = 1; off < NCHUNK; off <<= 1) {
        float tb = (c >= off) ? bufB[c - off] : 0.f;
        float ta = (c >= off) ? bufA[c - off] : 0.f;
        __syncthreads();
        bufB[c] += tb;
        bufA[c] += ta;
        __syncthreads();
    }
    g_chunkB[c * 65 + d] = bufB[c] - origB;
    g_chunkA[c * 65 + d] = bufA[NCHUNK - 1 - c] - origA;
}

__global__ void scan3() {
    __shared__ float sA[64], sB[64];
    __shared__ int sI[64];
    int c = blockIdx.x, tid = threadIdx.x;
    if (tid < 64) {
        sA[tid] = g_A[c * 64 + tid];
        sB[tid] = g_B[c * 64 + tid];
        sI[tid] = g_sidx[c * 64 + tid];
    }
    __syncthreads();
    if (tid <= 64) {
        int d = tid;
        float run = g_chunkB[c * 65 + d];
        #pragma unroll 4
        for (int mq = 0; mq < 64; ++mq) {
            size_t kk = (size_t)(c * 64 + mq);
            g_preB[kk * 65 + d] = run;
            float xv = (d < 64) ? g_hlast[sI[mq] * 64 + d] : 1.f;
            run += sB[mq] * xv;
        }
        if (c == NCHUNK - 1) g_preB[(size_t)NROWS * 65 + d] = run;
        float runA = g_chunkA[c * 65 + d];
        #pragma unroll 4
        for (int mq = 63; mq >= 0; --mq) {
            float xv = (d < 64) ? g_hlast[sI[mq] * 64 + d] : 1.f;
            runA += sA[mq] * xv;
            g_suffA[(size_t)(c * 64 + mq) * 65 + d] = runA;
        }
        if (c == NCHUNK - 1) g_suffA[(size_t)NROWS * 65 + d] = 0.f;
    }
}

__global__ void __launch_bounds__(256)
final_kernel(const float* __restrict__ Wfc, const float* __restrict__ bfc,
             const float* __restrict__ Wout, const float* __restrict__ bout,
             float* __restrict__ out) {
    __shared__ float sWfcT[64 * 65];
    __shared__ float sWo[64], sBfc[64];
    __shared__ float sZ[8][64];
    int tid = threadIdx.x;
    for (int idx = tid; idx < 4096; idx += 256) {
        int cc = idx >> 6, kq = idx & 63;
        sWfcT[kq * 65 + cc] = Wfc[idx];
    }
    if (tid < 64) { sWo[tid] = Wout[tid]; sBfc[tid] = bfc[tid]; }
    __syncthreads();

    int wy = tid >> 5, l = tid & 31;
    int i = blockIdx.x * 8 + wy;
    float smax = g_s1sorted[NROWS - 1];
    float s2 = g_s2[i];
    float thr = -s2;

    int kk = 0;
    #pragma unroll
    for (int st = 4096; st > 0; st >>= 1)
        if (kk + st <= NROWS && g_s1sorted[kk + st - 1] <= thr) kk += st;

    float u = s2 + smax;
    float fA, fB;
    if (u > 0.f) { fA = 1.f;               fB = __expf(-0.99f * u); }
    else         { fA = __expf(0.99f * u); fB = 1.f; }

    const float* suff = &g_suffA[(size_t)kk * 65];
    const float* pre  = &g_preB[(size_t)kk * 65];
    float inv = __fdividef(1.f, fA * suff[64] + fB * pre[64]);
    #pragma unroll
    for (int h = 0; h < 2; ++h) {
        int d = l + h * 32;
        sZ[wy][d] = (fA * suff[d] + fB * pre[d]) * inv + g_hlast[i * 64 + d];
    }
    __syncwarp();

    float yp = 0.f;
    #pragma unroll
    for (int h = 0; h < 2; ++h) {
        int c = l + h * 32;
        float dot = sBfc[c];
        #pragma unroll 16
        for (int kq = 0; kq < 64; ++kq) dot += sZ[wy][kq] * sWfcT[kq * 65 + c];
        dot = dot > 0.f ? dot : 0.01f * dot;
        yp += dot * sWo[c];
    }
    #pragma unroll
    for (int o = 16; o; o >>= 1) yp += __shfl_xor_sync(0xffffffffu, yp, o);
    if (l == 0) out[i] = yp + bout[0];
}

// =======================================================================
extern "C" void kernel_launch(void* const* d_in, const int* in_sizes, int n_in,
                              void* d_out, int out_size) {
    const float* x    = (const float*)d_in[0];
    const float* Wih0 = (const float*)d_in[1];
    const float* Whh0 = (const float*)d_in[2];
    const float* bih0 = (const float*)d_in[3];
    const float* bhh0 = (const float*)d_in[4];
    const float* Wih1 = (const float*)d_in[5];
    const float* Whh1 = (const float*)d_in[6];
    const float* bih1 = (const float*)d_in[7];
    const float* bhh1 = (const float*)d_in[8];
    const float* Wt   = (const float*)d_in[9];
    const float* bt   = (const float*)d_in[10];
    const float* a    = (const float*)d_in[11];
    const float* Wfc  = (const float*)d_in[12];
    const float* bfc  = (const float*)d_in[13];
    const float* Wout = (const float*)d_in[14];
    const float* bout = (const float*)d_in[15];
    float* out = (float*)d_out;

    const int SM_L0 = 80 * 512 + 32768 + 1024;    // 74752 B
    const int SM_L1 = 128 * 512 + 32768 + 1024;   // 99328 B
    const int SM_SORT = NROWS * 8;

    cudaFuncSetAttribute(lstm_mma<80, 5, 6, 0>, cudaFuncAttributeMaxDynamicSharedMemorySize, SM_L0);
    cudaFuncSetAttribute(lstm_mma<128, 8, 64, 1>, cudaFuncAttributeMaxDynamicSharedMemorySize, SM_L1);
    cudaFuncSetAttribute(sort_kernel, cudaFuncAttributeMaxDynamicSharedMemorySize, SM_SORT);

    lstm_mma<80, 5, 6, 0><<<NBLK, 512, SM_L0>>>(x, Wih0, Whh0, bih0, bhh0);
    lstm_mma<128, 8, 64, 1><<<NBLK, 512, SM_L1>>>(x, Wih1, Whh1, bih1, bhh1);
    prep1<<<1, 128>>>(Wt, bt, a);
    prep2<<<NROWS / 8, 256>>>();
    sort_kernel<<<1, 1024, SM_SORT>>>();
    scan1<<<NCHUNK, 128>>>();
    scan2<<<65, NCHUNK>>>();
    scan3<<<NCHUNK, 128>>>();
    final_kernel<<<NROWS / 8, 256>>>(Wfc, bfc, Wout, bout, out);
}

// round 13
// speedup vs baseline: 1.6068x; 1.0513x over previous
#include <cuda_runtime.h>
#include <cuda_fp16.h>
#include <math.h>
#include <stdint.h>

#define NROWS 8192
#define TT    60
#define NCHUNK 128
#define NBLK  128

// -------- device scratch --------
__device__ float g_hlast[NROWS * 64];
__device__ float g_s1[NROWS];
__device__ float g_s2[NROWS];
__device__ float g_v1[64];
__device__ float g_v2[64];
__device__ float g_c12[2];
__device__ float g_s1sorted[NROWS];
__device__ int   g_sidx[NROWS];
__device__ float g_A[NROWS];
__device__ float g_B[NROWS];
__device__ float g_chunkA[NCHUNK * 65];
__device__ float g_chunkB[NCHUNK * 65];
__device__ float g_preB[(size_t)(NROWS + 1) * 65];
__device__ float g_suffA[(size_t)(NROWS + 1) * 65];

__device__ __forceinline__ float tanha(float x) {
    float r;
    asm("tanh.approx.f32 %0, %1;" : "=f"(r) : "f"(x));
    return r;
}
__device__ __forceinline__ float siga(float x) { return fmaf(tanha(0.5f * x), 0.5f, 0.5f); }

// -------- warp-MMA helpers --------
__device__ __forceinline__ uint32_t smem_u32(const void* p) {
    uint32_t a;
    asm("{ .reg .u64 t; cvta.to.shared.u64 t, %1; cvt.u32.u64 %0, t; }" : "=r"(a) : "l"(p));
    return a;
}
__device__ __forceinline__ void barg(int id) {
    asm volatile("bar.sync %0, 128;" :: "r"(id) : "memory");
}
__device__ __forceinline__ void ldsm4(uint32_t* r, uint32_t a) {
    asm volatile("ldmatrix.sync.aligned.m8n8.x4.shared.b16 {%0,%1,%2,%3}, [%4];"
                 : "=r"(r[0]), "=r"(r[1]), "=r"(r[2]), "=r"(r[3]) : "r"(a));
}
__device__ __forceinline__ void ldsm4t(uint32_t* r, uint32_t a) {
    asm volatile("ldmatrix.sync.aligned.m8n8.x4.trans.shared.b16 {%0,%1,%2,%3}, [%4];"
                 : "=r"(r[0]), "=r"(r[1]), "=r"(r[2]), "=r"(r[3]) : "r"(a));
}
__device__ __forceinline__ void mma16816(float* d, const uint32_t* a, const uint32_t* b) {
    asm volatile(
        "mma.sync.aligned.m16n8k16.row.col.f32.f16.f16.f32 "
        "{%0,%1,%2,%3}, {%4,%5,%6,%7}, {%8,%9}, {%0,%1,%2,%3};"
        : "+f"(d[0]), "+f"(d[1]), "+f"(d[2]), "+f"(d[3])
        : "r"(a[0]), "r"(a[1]), "r"(a[2]), "r"(a[3]), "r"(b[0]), "r"(b[1]));
}
__device__ __forceinline__ uint16_t f2h(float v) {
    __half h = __float2half_rn(v);
    return *(uint16_t*)&h;
}
// A tile [64 rows][128 k] fp16, 256B/row, swizzled 16B chunks
__device__ __forceinline__ uint32_t offA(int r, int k) {
    int ck = k >> 3;
    return (uint32_t)(r * 256 + (((ck & 8) | ((ck ^ r) & 7)) << 4) + (k & 7) * 2);
}
// W tile [k][256 n] fp16, 512B/row
__device__ __forceinline__ uint32_t offW(int k, int n) {
    int cn = n >> 3;
    return (uint32_t)(k * 512 + (((cn & 24) | ((cn ^ k) & 7)) << 4) + (n & 7) * 2);
}

// SMEM layout (bytes)
#define S_W0   0
#define S_W1   40960
#define S_A0   106496
#define S_A1   139264
#define S_B0   172032
#define S_B1   173056
#define SM_TOT 174080

// =======================================================================
// FUSED two-layer HMMA LSTM: 128 blocks x 64 rows, 512 threads.
// rw = wid>>2 (row-group), cg = wid&3 (scheduler) -> per-SMSP drift.
// Per step: MMA-L0 (A0[p], W0, 5 chunks) -> cell-L0 -> h0 into A0[1-p]
// (k0..63, own recurrence) AND A1[p] (k64..127, L1 input) -> group bar ->
// MMA-L1 (A1[p] = [h1(t-1) | h0(t)], W1, 8 chunks) -> cell-L1 -> h1 into
// A1[1-p] k0..63 -> group bar. h0 never touches gmem.
// =======================================================================
__global__ void __launch_bounds__(512, 1)
lstm_fused(const float* __restrict__ xin,
           const float* __restrict__ Wih0, const float* __restrict__ Whh0,
           const float* __restrict__ bih0, const float* __restrict__ bhh0,
           const float* __restrict__ Wih1, const float* __restrict__ Whh1,
           const float* __restrict__ bih1, const float* __restrict__ bhh1) {
    extern __shared__ char smem[];
    const uint32_t sbase = smem_u32(smem);

    const int tid = threadIdx.x, lane = tid & 31, wid = tid >> 5;
    const int rw = wid >> 2, cg = wid & 3;
    const int t4 = lane & 3, g8 = lane >> 2;
    const int r0 = rw * 16;
    const int rowb = blockIdx.x * 64;
    const int row_st = r0 + g8 + ((t4 & 1) ? 8 : 0);
    const int m = lane >> 3, q = lane & 7;
    const int t128 = cg * 32 + lane;
    const int barid = rw + 1;

    // ---- stage W0 (80 k-rows) and W1 (128 k-rows), permuted n=4j+type ----
    for (int idx = tid; idx < 80 * 256; idx += 512) {
        int k = idx >> 8, n = idx & 255;
        int go = (n & 3) * 64 + (n >> 2);
        float w = (k < 64) ? Whh0[go * 64 + k]
                           : ((k - 64 < 6) ? Wih0[go * 6 + (k - 64)] : 0.f);
        *(uint16_t*)(smem + S_W0 + offW(k, n)) = f2h(w);
    }
    for (int idx = tid; idx < 128 * 256; idx += 512) {
        int k = idx >> 8, n = idx & 255;
        int go = (n & 3) * 64 + (n >> 2);
        float w = (k < 64) ? Whh1[go * 64 + k] : Wih1[go * 64 + (k - 64)];
        *(uint16_t*)(smem + S_W1 + offW(k, n)) = f2h(w);
    }
    // zero A0 + A1 (64KB contiguous from S_A0)
    for (int i = tid; i < 4096; i += 512) ((uint4*)(smem + S_A0))[i] = make_uint4(0, 0, 0, 0);
    if (tid < 256) {
        int go = (tid & 3) * 64 + (tid >> 2);
        ((float*)(smem + S_B0))[tid] = bih0[go] + bhh0[go];
        ((float*)(smem + S_B1))[tid] = bih1[go] + bhh1[go];
    }
    __syncthreads();

    // group-local x staging (rows r0..r0+15, 6 feats -> 96 of 128 threads)
    const int xrow = r0 + t128 / 6, xd = t128 - (t128 / 6) * 6;
    float xf = 0.f;
    auto pfx = [&](int t) {
        if (t128 < 96) xf = xin[((size_t)(rowb + xrow) * TT + t) * 6 + xd];
    };
    auto stx = [&](int buf) {
        if (t128 < 96)
            *(uint16_t*)(smem + S_A0 + buf * 16384 + offA(xrow, 64 + xd)) = f2h(xf);
    };

    pfx(0);
    stx(0);
    __syncthreads();

    float c0[8], c1[8];
    #pragma unroll
    for (int nt = 0; nt < 8; ++nt) { c0[nt] = 0.f; c1[nt] = 0.f; }

    const int kb = cg * 16 + ((t4 & 2) ? 8 : 0);
    float d[8][4];

    auto mma_phase = [&](uint32_t abase, uint32_t wbase, int nch, int biasofs) {
        #pragma unroll
        for (int nt = 0; nt < 8; ++nt) {
            float2 b2 = *(const float2*)(smem + biasofs + (cg * 64 + nt * 8 + t4 * 2) * 4);
            d[nt][0] = b2.x; d[nt][1] = b2.y; d[nt][2] = b2.x; d[nt][3] = b2.y;
        }
        #pragma unroll 2
        for (int ch = 0; ch < nch; ++ch) {
            int ar = r0 + (m & 1) * 8 + q;
            int ak = ch * 16 + (m >> 1) * 8;
            uint32_t av[4];
            ldsm4(av, abase + offA(ar, ak));
            int bk = ch * 16 + (m & 1) * 8 + q;
            uint32_t bw[16];
            #pragma unroll
            for (int pp = 0; pp < 4; ++pp)
                ldsm4t(&bw[4 * pp], wbase + offW(bk, cg * 64 + (2 * pp + (m >> 1)) * 8));
            #pragma unroll
            for (int nt = 0; nt < 8; ++nt) mma16816(d[nt], av, &bw[2 * nt]);
        }
    };

    // cell: gates in d -> h fp16 pk (8 j-cols of row_st); updates cst
    auto cell_phase = [&](float* cst, float* hf, uint4& pk) {
        uint32_t w0a[8], w1a[8];
        #pragma unroll
        for (int nt = 0; nt < 8; ++nt) {
            float e0 = __shfl_xor_sync(0xffffffffu, d[nt][0], 1);
            float e1 = __shfl_xor_sync(0xffffffffu, d[nt][1], 1);
            float e2 = __shfl_xor_sync(0xffffffffu, d[nt][2], 1);
            float e3 = __shfl_xor_sync(0xffffffffu, d[nt][3], 1);
            float iv, fv, gv, ov;
            if (t4 & 1) { iv = e2; fv = e3; gv = d[nt][2]; ov = d[nt][3]; }
            else        { iv = d[nt][0]; fv = d[nt][1]; gv = e0; ov = e1; }
            float cc = siga(fv) * cst[nt] + siga(iv) * tanha(gv);
            cst[nt] = cc;
            float hh = siga(ov) * tanha(cc);
            hf[nt] = hh;
            uint32_t hpk = (uint32_t)f2h(hh);
            uint32_t rv = __shfl_xor_sync(0xffffffffu, hpk, 2);
            w0a[nt] = (t4 & 2) ? rv : hpk;
            w1a[nt] = (t4 & 2) ? hpk : rv;
        }
        const int ntb = (t4 & 2) ? 4 : 0;
        pk = make_uint4(w0a[ntb] | (w1a[ntb] << 16),
                        w0a[ntb + 1] | (w1a[ntb + 1] << 16),
                        w0a[ntb + 2] | (w1a[ntb + 2] << 16),
                        w0a[ntb + 3] | (w1a[ntb + 3] << 16));
    };

    #pragma unroll 1
    for (int t = 0; t < TT; ++t) {
        const int p = t & 1;
        const uint32_t a0r = sbase + (uint32_t)(S_A0 + p * 16384);
        char* a0w = smem + S_A0 + (1 - p) * 16384;
        const uint32_t a1r = sbase + (uint32_t)(S_A1 + p * 16384);
        char* a1cur = smem + S_A1 + p * 16384;       // receives h0(t) at k64+
        char* a1w = smem + S_A1 + (1 - p) * 16384;   // receives h1(t) at k0..63

        if (t < TT - 1) pfx(t + 1);  // LDG overlapped with L0 MMA

        // ---- layer 0 ----
        mma_phase(a0r, sbase + S_W0, 5, S_B0);
        float hf[8];
        uint4 pk;
        cell_phase(c0, hf, pk);
        if (t < TT - 1) {
            *(uint4*)(a0w + offA(row_st, kb)) = pk;  // own recurrence
            stx(1 - p);                              // x(t+1)
        }
        *(uint4*)(a1cur + offA(row_st, 64 + kb)) = pk;  // hand h0(t) to L1
        barg(barid);  // h0 visible to row-group before L1 MMA

        // ---- layer 1 ----
        mma_phase(a1r, sbase + S_W1, 8, S_B1);
        cell_phase(c1, hf, pk);
        if (t < TT - 1) *(uint4*)(a1w + offA(row_st, kb)) = pk;
        else {
            #pragma unroll
            for (int nt = 0; nt < 8; ++nt)
                g_hlast[(rowb + row_st) * 64 + cg * 16 + 2 * nt + (t4 >> 1)] = hf[nt];
        }
        barg(barid);  // end of step
    }
}

// =======================================================================
// GAT prep + O(N) attention + head (passing versions, unchanged)
// =======================================================================
__global__ void prep1(const float* __restrict__ Wt, const float* __restrict__ bt,
                      const float* __restrict__ a) {
    int tid = threadIdx.x;
    if (tid < 64) {
        float v = 0.f;
        for (int g = 0; g < 64; ++g) v += Wt[g * 64 + tid] * a[g];
        g_v1[tid] = v;
    } else if (tid < 128) {
        int k = tid - 64;
        float v = 0.f;
        for (int g = 0; g < 64; ++g) v += Wt[g * 64 + k] * a[64 + g];
        g_v2[k] = v;
    }
    if (tid == 0) {
        float c = 0.f;
        for (int g = 0; g < 64; ++g) c += bt[g] * a[g];
        g_c12[0] = c;
    }
    if (tid == 1) {
        float c = 0.f;
        for (int g = 0; g < 64; ++g) c += bt[g] * a[64 + g];
        g_c12[1] = c;
    }
}

__global__ void prep2() {
    int lane = threadIdx.x & 31, w = threadIdx.x >> 5;
    int r = blockIdx.x * 8 + w;
    float l0 = g_hlast[r * 64 + lane], l1 = g_hlast[r * 64 + 32 + lane];
    float p1 = l0 * g_v1[lane] + l1 * g_v1[lane + 32];
    float p2 = l0 * g_v2[lane] + l1 * g_v2[lane + 32];
    #pragma unroll
    for (int o = 16; o; o >>= 1) {
        p1 += __shfl_xor_sync(0xffffffffu, p1, o);
        p2 += __shfl_xor_sync(0xffffffffu, p2, o);
    }
    if (lane == 0) {
        g_s1[r] = p1 + g_c12[0];
        g_s2[r] = p2 + g_c12[1];
    }
}

__global__ void __launch_bounds__(1024, 1) sort_kernel() {
    extern __shared__ char sraw[];
    float* k = (float*)sraw;
    int* v = (int*)(sraw + NROWS * 4);
    int tid = threadIdx.x;
    for (int i = tid; i < NROWS; i += 1024) { k[i] = g_s1[i]; v[i] = i; }
    for (int size = 2; size <= NROWS; size <<= 1) {
        for (int stride = size >> 1; stride > 0; stride >>= 1) {
            __syncthreads();
            #pragma unroll
            for (int e = 0; e < NROWS / 1024; ++e) {
                int i = e * 1024 + tid;
                int j = i ^ stride;
                if (j > i) {
                    bool up = ((i & size) == 0);
                    float ki = k[i], kj = k[j];
                    if ((ki > kj) == up) {
                        k[i] = kj; k[j] = ki;
                        int t = v[i]; v[i] = v[j]; v[j] = t;
                    }
                }
            }
        }
    }
    __syncthreads();
    for (int i = tid; i < NROWS; i += 1024) { g_s1sorted[i] = k[i]; g_sidx[i] = v[i]; }
}

__global__ void scan1() {
    __shared__ float sA[64], sB[64];
    __shared__ int sI[64];
    int c = blockIdx.x, tid = threadIdx.x;
    if (tid < 64) {
        float smax = g_s1sorted[NROWS - 1];
        float key = g_s1sorted[c * 64 + tid];
        float A = __expf(key - smax);
        float B = __expf(0.01f * (key - smax));
        sA[tid] = A; sB[tid] = B;
        sI[tid] = g_sidx[c * 64 + tid];
        g_A[c * 64 + tid] = A;
        g_B[c * 64 + tid] = B;
    }
    __syncthreads();
    if (tid <= 64) {
        float sa = 0.f, sb = 0.f;
        #pragma unroll 4
        for (int mq = 0; mq < 64; ++mq) {
            float xv = (tid < 64) ? g_hlast[sI[mq] * 64 + tid] : 1.f;
            sa += sA[mq] * xv;
            sb += sB[mq] * xv;
        }
        g_chunkA[c * 65 + tid] = sa;
        g_chunkB[c * 65 + tid] = sb;
    }
}

__global__ void scan2() {
    __shared__ float bufB[NCHUNK], bufA[NCHUNK];
    int d = blockIdx.x;
    int c = threadIdx.x;
    float origB = g_chunkB[c * 65 + d];
    float origA = g_chunkA[c * 65 + d];
    bufB[c] = origB;
    bufA[NCHUNK - 1 - c] = origA;
    __syncthreads();
    #pragma unroll
    for (int off = 1; off < NCHUNK; off <<= 1) {
        float tb = (c >= off) ? bufB[c - off] : 0.f;
        float ta = (c >= off) ? bufA[c - off] : 0.f;
        __syncthreads();
        bufB[c] += tb;
        bufA[c] += ta;
        __syncthreads();
    }
    g_chunkB[c * 65 + d] = bufB[c] - origB;
    g_chunkA[c * 65 + d] = bufA[NCHUNK - 1 - c] - origA;
}

__global__ void scan3() {
    __shared__ float sA[64], sB[64];
    __shared__ int sI[64];
    int c = blockIdx.x, tid = threadIdx.x;
    if (tid < 64) {
        sA[tid] = g_A[c * 64 + tid];
        sB[tid] = g_B[c * 64 + tid];
        sI[tid] = g_sidx[c * 64 + tid];
    }
    __syncthreads();
    if (tid <= 64) {
        int d = tid;
        float run = g_chunkB[c * 65 + d];
        #pragma unroll 4
        for (int mq = 0; mq < 64; ++mq) {
            size_t kk = (size_t)(c * 64 + mq);
            g_preB[kk * 65 + d] = run;
            float xv = (d < 64) ? g_hlast[sI[mq] * 64 + d] : 1.f;
            run += sB[mq] * xv;
        }
        if (c == NCHUNK - 1) g_preB[(size_t)NROWS * 65 + d] = run;
        float runA = g_chunkA[c * 65 + d];
        #pragma unroll 4
        for (int mq = 63; mq >= 0; --mq) {
            float xv = (d < 64) ? g_hlast[sI[mq] * 64 + d] : 1.f;
            runA += sA[mq] * xv;
            g_suffA[(size_t)(c * 64 + mq) * 65 + d] = runA;
        }
        if (c == NCHUNK - 1) g_suffA[(size_t)NROWS * 65 + d] = 0.f;
    }
}

__global__ void __launch_bounds__(256)
final_kernel(const float* __restrict__ Wfc, const float* __restrict__ bfc,
             const float* __restrict__ Wout, const float* __restrict__ bout,
             float* __restrict__ out) {
    __shared__ float sWfcT[64 * 65];
    __shared__ float sWo[64], sBfc[64];
    __shared__ float sZ[8][64];
    int tid = threadIdx.x;
    for (int idx = tid; idx < 4096; idx += 256) {
        int cc = idx >> 6, kq = idx & 63;
        sWfcT[kq * 65 + cc] = Wfc[idx];
    }
    if (tid < 64) { sWo[tid] = Wout[tid]; sBfc[tid] = bfc[tid]; }
    __syncthreads();

    int wy = tid >> 5, l = tid & 31;
    int i = blockIdx.x * 8 + wy;
    float smax = g_s1sorted[NROWS - 1];
    float s2 = g_s2[i];
    float thr = -s2;

    int kk = 0;
    #pragma unroll
    for (int st = 4096; st > 0; st >>= 1)
        if (kk + st <= NROWS && g_s1sorted[kk + st - 1] <= thr) kk += st;

    float u = s2 + smax;
    float fA, fB;
    if (u > 0.f) { fA = 1.f;               fB = __expf(-0.99f * u); }
    else         { fA = __expf(0.99f * u); fB = 1.f; }

    const float* suff = &g_suffA[(size_t)kk * 65];
    const float* pre  = &g_preB[(size_t)kk * 65];
    float inv = __fdividef(1.f, fA * suff[64] + fB * pre[64]);
    #pragma unroll
    for (int h = 0; h < 2; ++h) {
        int d = l + h * 32;
        sZ[wy][d] = (fA * suff[d] + fB * pre[d]) * inv + g_hlast[i * 64 + d];
    }
    __syncwarp();

    float yp = 0.f;
    #pragma unroll
    for (int h = 0; h < 2; ++h) {
        int c = l + h * 32;
        float dot = sBfc[c];
        #pragma unroll 16
        for (int kq = 0; kq < 64; ++kq) dot += sZ[wy][kq] * sWfcT[kq * 65 + c];
        dot = dot > 0.f ? dot : 0.01f * dot;
        yp += dot * sWo[c];
    }
    #pragma unroll
    for (int o = 16; o; o >>= 1) yp += __shfl_xor_sync(0xffffffffu, yp, o);
    if (l == 0) out[i] = yp + bout[0];
}

// =======================================================================
extern "C" void kernel_launch(void* const* d_in, const int* in_sizes, int n_in,
                              void* d_out, int out_size) {
    const float* x    = (const float*)d_in[0];
    const float* Wih0 = (const float*)d_in[1];
    const float* Whh0 = (const float*)d_in[2];
    const float* bih0 = (const float*)d_in[3];
    const float* bhh0 = (const float*)d_in[4];
    const float* Wih1 = (const float*)d_in[5];
    const float* Whh1 = (const float*)d_in[6];
    const float* bih1 = (const float*)d_in[7];
    const float* bhh1 = (const float*)d_in[8];
    const float* Wt   = (const float*)d_in[9];
    const float* bt   = (const float*)d_in[10];
    const float* a    = (const float*)d_in[11];
    const float* Wfc  = (const float*)d_in[12];
    const float* bfc  = (const float*)d_in[13];
    const float* Wout = (const float*)d_in[14];
    const float* bout = (const float*)d_in[15];
    float* out = (float*)d_out;

    const int SM_SORT = NROWS * 8;
    cudaFuncSetAttribute(lstm_fused, cudaFuncAttributeMaxDynamicSharedMemorySize, SM_TOT);
    cudaFuncSetAttribute(sort_kernel, cudaFuncAttributeMaxDynamicSharedMemorySize, SM_SORT);

    lstm_fused<<<NBLK, 512, SM_TOT>>>(x, Wih0, Whh0, bih0, bhh0,
                                      Wih1, Whh1, bih1, bhh1);
    prep1<<<1, 128>>>(Wt, bt, a);
    prep2<<<NROWS / 8, 256>>>();
    sort_kernel<<<1, 1024, SM_SORT>>>();
    scan1<<<NCHUNK, 128>>>();
    scan2<<<65, NCHUNK>>>();
    scan3<<<NCHUNK, 128>>>();
    final_kernel<<<NROWS / 8, 256>>>(Wfc, bfc, Wout, bout, out);
}

// round 14
// speedup vs baseline: 1.7386x; 1.0820x over previous
#include <cuda_runtime.h>
#include <cuda_fp16.h>
#include <math.h>
#include <stdint.h>

#define NROWS 8192
#define TT    60
#define NCHUNK 128
#define NBLK  128

// -------- device scratch --------
__device__ float g_hlast[NROWS * 64];
__device__ float g_s1[NROWS];
__device__ float g_s2[NROWS];
__device__ float g_v1[64];
__device__ float g_v2[64];
__device__ float g_c12[2];
__device__ float g_s1sorted[NROWS];
__device__ int   g_sidx[NROWS];
__device__ float g_A[NROWS];
__device__ float g_B[NROWS];
__device__ float g_chunkA[NCHUNK * 65];
__device__ float g_chunkB[NCHUNK * 65];
__device__ float g_preB[(size_t)(NROWS + 1) * 65];
__device__ float g_suffA[(size_t)(NROWS + 1) * 65];

__device__ __forceinline__ float tanha(float x) {
    float r;
    asm("tanh.approx.f32 %0, %1;" : "=f"(r) : "f"(x));
    return r;
}
__device__ __forceinline__ float siga(float x) { return fmaf(tanha(0.5f * x), 0.5f, 0.5f); }

// -------- warp-MMA helpers --------
__device__ __forceinline__ uint32_t smem_u32(const void* p) {
    uint32_t a;
    asm("{ .reg .u64 t; cvta.to.shared.u64 t, %1; cvt.u32.u64 %0, t; }" : "=r"(a) : "l"(p));
    return a;
}
__device__ __forceinline__ void barg(int id) {
    asm volatile("bar.sync %0, 128;" :: "r"(id) : "memory");
}
__device__ __forceinline__ void ldsm4(uint32_t* r, uint32_t a) {
    asm volatile("ldmatrix.sync.aligned.m8n8.x4.shared.b16 {%0,%1,%2,%3}, [%4];"
                 : "=r"(r[0]), "=r"(r[1]), "=r"(r[2]), "=r"(r[3]) : "r"(a));
}
__device__ __forceinline__ void ldsm4t(uint32_t* r, uint32_t a) {
    asm volatile("ldmatrix.sync.aligned.m8n8.x4.trans.shared.b16 {%0,%1,%2,%3}, [%4];"
                 : "=r"(r[0]), "=r"(r[1]), "=r"(r[2]), "=r"(r[3]) : "r"(a));
}
__device__ __forceinline__ void mma16816(float* d, const uint32_t* a, const uint32_t* b) {
    asm volatile(
        "mma.sync.aligned.m16n8k16.row.col.f32.f16.f16.f32 "
        "{%0,%1,%2,%3}, {%4,%5,%6,%7}, {%8,%9}, {%0,%1,%2,%3};"
        : "+f"(d[0]), "+f"(d[1]), "+f"(d[2]), "+f"(d[3])
        : "r"(a[0]), "r"(a[1]), "r"(a[2]), "r"(a[3]), "r"(b[0]), "r"(b[1]));
}
__device__ __forceinline__ uint16_t f2h(float v) {
    __half h = __float2half_rn(v);
    return *(uint16_t*)&h;
}
// A tile [64 rows][128 k] fp16, 256B/row, swizzled 16B chunks
__device__ __forceinline__ uint32_t offA(int r, int k) {
    int ck = k >> 3;
    return (uint32_t)(r * 256 + (((ck & 8) | ((ck ^ r) & 7)) << 4) + (k & 7) * 2);
}
// W tile [k][256 n] fp16, 512B/row
__device__ __forceinline__ uint32_t offW(int k, int n) {
    int cn = n >> 3;
    return (uint32_t)(k * 512 + (((cn & 24) | ((cn ^ k) & 7)) << 4) + (n & 7) * 2);
}

// SMEM layout (bytes)
#define S_W0   0
#define S_W1   40960
#define S_A0   106496
#define S_A1   139264
#define S_B0   172032
#define S_B1   173056
#define SM_TOT 174080

// =======================================================================
// FUSED two-layer HMMA LSTM (identical to R13-passing version)
// =======================================================================
__global__ void __launch_bounds__(512, 1)
lstm_fused(const float* __restrict__ xin,
           const float* __restrict__ Wih0, const float* __restrict__ Whh0,
           const float* __restrict__ bih0, const float* __restrict__ bhh0,
           const float* __restrict__ Wih1, const float* __restrict__ Whh1,
           const float* __restrict__ bih1, const float* __restrict__ bhh1) {
    extern __shared__ char smem[];
    const uint32_t sbase = smem_u32(smem);

    const int tid = threadIdx.x, lane = tid & 31, wid = tid >> 5;
    const int rw = wid >> 2, cg = wid & 3;
    const int t4 = lane & 3, g8 = lane >> 2;
    const int r0 = rw * 16;
    const int rowb = blockIdx.x * 64;
    const int row_st = r0 + g8 + ((t4 & 1) ? 8 : 0);
    const int m = lane >> 3, q = lane & 7;
    const int t128 = cg * 32 + lane;
    const int barid = rw + 1;

    for (int idx = tid; idx < 80 * 256; idx += 512) {
        int k = idx >> 8, n = idx & 255;
        int go = (n & 3) * 64 + (n >> 2);
        float w = (k < 64) ? Whh0[go * 64 + k]
                           : ((k - 64 < 6) ? Wih0[go * 6 + (k - 64)] : 0.f);
        *(uint16_t*)(smem + S_W0 + offW(k, n)) = f2h(w);
    }
    for (int idx = tid; idx < 128 * 256; idx += 512) {
        int k = idx >> 8, n = idx & 255;
        int go = (n & 3) * 64 + (n >> 2);
        float w = (k < 64) ? Whh1[go * 64 + k] : Wih1[go * 64 + (k - 64)];
        *(uint16_t*)(smem + S_W1 + offW(k, n)) = f2h(w);
    }
    for (int i = tid; i < 4096; i += 512) ((uint4*)(smem + S_A0))[i] = make_uint4(0, 0, 0, 0);
    if (tid < 256) {
        int go = (tid & 3) * 64 + (tid >> 2);
        ((float*)(smem + S_B0))[tid] = bih0[go] + bhh0[go];
        ((float*)(smem + S_B1))[tid] = bih1[go] + bhh1[go];
    }
    __syncthreads();

    const int xrow = r0 + t128 / 6, xd = t128 - (t128 / 6) * 6;
    float xf = 0.f;
    auto pfx = [&](int t) {
        if (t128 < 96) xf = xin[((size_t)(rowb + xrow) * TT + t) * 6 + xd];
    };
    auto stx = [&](int buf) {
        if (t128 < 96)
            *(uint16_t*)(smem + S_A0 + buf * 16384 + offA(xrow, 64 + xd)) = f2h(xf);
    };

    pfx(0);
    stx(0);
    __syncthreads();

    float c0[8], c1[8];
    #pragma unroll
    for (int nt = 0; nt < 8; ++nt) { c0[nt] = 0.f; c1[nt] = 0.f; }

    const int kb = cg * 16 + ((t4 & 2) ? 8 : 0);
    float d[8][4];

    auto mma_phase = [&](uint32_t abase, uint32_t wbase, int nch, int biasofs) {
        #pragma unroll
        for (int nt = 0; nt < 8; ++nt) {
            float2 b2 = *(const float2*)(smem + biasofs + (cg * 64 + nt * 8 + t4 * 2) * 4);
            d[nt][0] = b2.x; d[nt][1] = b2.y; d[nt][2] = b2.x; d[nt][3] = b2.y;
        }
        #pragma unroll 2
        for (int ch = 0; ch < nch; ++ch) {
            int ar = r0 + (m & 1) * 8 + q;
            int ak = ch * 16 + (m >> 1) * 8;
            uint32_t av[4];
            ldsm4(av, abase + offA(ar, ak));
            int bk = ch * 16 + (m & 1) * 8 + q;
            uint32_t bw[16];
            #pragma unroll
            for (int pp = 0; pp < 4; ++pp)
                ldsm4t(&bw[4 * pp], wbase + offW(bk, cg * 64 + (2 * pp + (m >> 1)) * 8));
            #pragma unroll
            for (int nt = 0; nt < 8; ++nt) mma16816(d[nt], av, &bw[2 * nt]);
        }
    };

    auto cell_phase = [&](float* cst, float* hf, uint4& pk) {
        uint32_t w0a[8], w1a[8];
        #pragma unroll
        for (int nt = 0; nt < 8; ++nt) {
            float e0 = __shfl_xor_sync(0xffffffffu, d[nt][0], 1);
            float e1 = __shfl_xor_sync(0xffffffffu, d[nt][1], 1);
            float e2 = __shfl_xor_sync(0xffffffffu, d[nt][2], 1);
            float e3 = __shfl_xor_sync(0xffffffffu, d[nt][3], 1);
            float iv, fv, gv, ov;
            if (t4 & 1) { iv = e2; fv = e3; gv = d[nt][2]; ov = d[nt][3]; }
            else        { iv = d[nt][0]; fv = d[nt][1]; gv = e0; ov = e1; }
            float cc = siga(fv) * cst[nt] + siga(iv) * tanha(gv);
            cst[nt] = cc;
            float hh = siga(ov) * tanha(cc);
            hf[nt] = hh;
            uint32_t hpk = (uint32_t)f2h(hh);
            uint32_t rv = __shfl_xor_sync(0xffffffffu, hpk, 2);
            w0a[nt] = (t4 & 2) ? rv : hpk;
            w1a[nt] = (t4 & 2) ? hpk : rv;
        }
        const int ntb = (t4 & 2) ? 4 : 0;
        pk = make_uint4(w0a[ntb] | (w1a[ntb] << 16),
                        w0a[ntb + 1] | (w1a[ntb + 1] << 16),
                        w0a[ntb + 2] | (w1a[ntb + 2] << 16),
                        w0a[ntb + 3] | (w1a[ntb + 3] << 16));
    };

    #pragma unroll 1
    for (int t = 0; t < TT; ++t) {
        const int p = t & 1;
        const uint32_t a0r = sbase + (uint32_t)(S_A0 + p * 16384);
        char* a0w = smem + S_A0 + (1 - p) * 16384;
        const uint32_t a1r = sbase + (uint32_t)(S_A1 + p * 16384);
        char* a1cur = smem + S_A1 + p * 16384;
        char* a1w = smem + S_A1 + (1 - p) * 16384;

        if (t < TT - 1) pfx(t + 1);

        mma_phase(a0r, sbase + S_W0, 5, S_B0);
        float hf[8];
        uint4 pk;
        cell_phase(c0, hf, pk);
        if (t < TT - 1) {
            *(uint4*)(a0w + offA(row_st, kb)) = pk;
            stx(1 - p);
        }
        *(uint4*)(a1cur + offA(row_st, 64 + kb)) = pk;
        barg(barid);

        mma_phase(a1r, sbase + S_W1, 8, S_B1);
        cell_phase(c1, hf, pk);
        if (t < TT - 1) *(uint4*)(a1w + offA(row_st, kb)) = pk;
        else {
            #pragma unroll
            for (int nt = 0; nt < 8; ++nt)
                g_hlast[(rowb + row_st) * 64 + cg * 16 + 2 * nt + (t4 >> 1)] = hf[nt];
        }
        barg(barid);
    }
}

// =======================================================================
// GAT prep
// =======================================================================
__global__ void prep1(const float* __restrict__ Wt, const float* __restrict__ bt,
                      const float* __restrict__ a) {
    int tid = threadIdx.x;
    if (tid < 64) {
        float v = 0.f;
        for (int g = 0; g < 64; ++g) v += Wt[g * 64 + tid] * a[g];
        g_v1[tid] = v;
    } else if (tid < 128) {
        int k = tid - 64;
        float v = 0.f;
        for (int g = 0; g < 64; ++g) v += Wt[g * 64 + k] * a[64 + g];
        g_v2[k] = v;
    }
    if (tid == 0) {
        float c = 0.f;
        for (int g = 0; g < 64; ++g) c += bt[g] * a[g];
        g_c12[0] = c;
    }
    if (tid == 1) {
        float c = 0.f;
        for (int g = 0; g < 64; ++g) c += bt[g] * a[64 + g];
        g_c12[1] = c;
    }
}

__global__ void prep2() {
    int lane = threadIdx.x & 31, w = threadIdx.x >> 5;
    int r = blockIdx.x * 8 + w;
    float l0 = g_hlast[r * 64 + lane], l1 = g_hlast[r * 64 + 32 + lane];
    float p1 = l0 * g_v1[lane] + l1 * g_v1[lane + 32];
    float p2 = l0 * g_v2[lane] + l1 * g_v2[lane + 32];
    #pragma unroll
    for (int o = 16; o; o >>= 1) {
        p1 += __shfl_xor_sync(0xffffffffu, p1, o);
        p2 += __shfl_xor_sync(0xffffffffu, p2, o);
    }
    if (lane == 0) {
        g_s1[r] = p1 + g_c12[0];
        g_s2[r] = p2 + g_c12[1];
    }
}

// packed 64-bit bitonic sort: key(sortable u32) | idx, register-local
// stages for stride<=4, padded smem layout phys(i)=i+(i>>3).
__device__ __forceinline__ int sphys(int i) { return i + (i >> 3); }

__global__ void __launch_bounds__(1024, 1) sort_kernel() {
    extern __shared__ unsigned long long sv[];
    int tid = threadIdx.x;
    for (int i = tid; i < NROWS; i += 1024) {
        uint32_t u = __float_as_uint(g_s1[i]);
        u = (u & 0x80000000u) ? ~u : (u | 0x80000000u);
        sv[sphys(i)] = ((unsigned long long)u << 32) | (uint32_t)i;
    }
    __syncthreads();

    const int base = tid * 8;          // logical base; sphys(base+e) = tid*9+e
    unsigned long long r[8];
    auto lda = [&]() {
        #pragma unroll
        for (int e = 0; e < 8; ++e) r[e] = sv[tid * 9 + e];
    };
    auto sta = [&]() {
        #pragma unroll
        for (int e = 0; e < 8; ++e) sv[tid * 9 + e] = r[e];
    };
    auto cas = [&](int a, int b, bool up) {
        if ((r[a] > r[b]) == up) { unsigned long long t = r[a]; r[a] = r[b]; r[b] = t; }
    };

    // sizes 2, 4, 8 fully in registers
    lda();
    cas(0, 1, true);  cas(2, 3, false); cas(4, 5, true);  cas(6, 7, false);
    cas(0, 2, true);  cas(1, 3, true);  cas(4, 6, false); cas(5, 7, false);
    cas(0, 1, true);  cas(2, 3, true);  cas(4, 5, false); cas(6, 7, false);
    {
        bool up8 = (tid & 1) == 0;
        cas(0, 4, up8); cas(1, 5, up8); cas(2, 6, up8); cas(3, 7, up8);
        cas(0, 2, up8); cas(1, 3, up8); cas(4, 6, up8); cas(5, 7, up8);
        cas(0, 1, up8); cas(2, 3, up8); cas(4, 5, up8); cas(6, 7, up8);
    }
    sta();

    for (int size = 16; size <= NROWS; size <<= 1) {
        for (int stride = size >> 1; stride >= 8; stride >>= 1) {
            __syncthreads();
            #pragma unroll
            for (int e = 0; e < 4; ++e) {
                int p = e * 1024 + tid;
                int i = ((p & ~(stride - 1)) << 1) | (p & (stride - 1));
                int j = i + stride;
                bool up = (i & size) == 0;
                unsigned long long vi = sv[sphys(i)], vj = sv[sphys(j)];
                if ((vi > vj) == up) { sv[sphys(i)] = vj; sv[sphys(j)] = vi; }
            }
        }
        __syncthreads();
        bool up = (base & size) == 0;
        lda();
        cas(0, 4, up); cas(1, 5, up); cas(2, 6, up); cas(3, 7, up);
        cas(0, 2, up); cas(1, 3, up); cas(4, 6, up); cas(5, 7, up);
        cas(0, 1, up); cas(2, 3, up); cas(4, 5, up); cas(6, 7, up);
        sta();
        __syncthreads();
    }

    for (int i = tid; i < NROWS; i += 1024) {
        unsigned long long v = sv[sphys(i)];
        uint32_t u = (uint32_t)(v >> 32);
        uint32_t fb = (u & 0x80000000u) ? (u & 0x7FFFFFFFu) : ~u;
        g_s1sorted[i] = __uint_as_float(fb);
        g_sidx[i] = (int)(v & 0xFFFFFFFFu);
    }
}

__global__ void scan1() {
    __shared__ float sA[64], sB[64];
    __shared__ int sI[64];
    int c = blockIdx.x, tid = threadIdx.x;
    if (tid < 64) {
        float smax = g_s1sorted[NROWS - 1];
        float key = g_s1sorted[c * 64 + tid];
        float A = __expf(key - smax);
        float B = __expf(0.01f * (key - smax));
        sA[tid] = A; sB[tid] = B;
        sI[tid] = g_sidx[c * 64 + tid];
        g_A[c * 64 + tid] = A;
        g_B[c * 64 + tid] = B;
    }
    __syncthreads();
    if (tid <= 64) {
        float sa = 0.f, sb = 0.f;
        #pragma unroll 4
        for (int mq = 0; mq < 64; ++mq) {
            float xv = (tid < 64) ? g_hlast[sI[mq] * 64 + tid] : 1.f;
            sa += sA[mq] * xv;
            sb += sB[mq] * xv;
        }
        g_chunkA[c * 65 + tid] = sa;
        g_chunkB[c * 65 + tid] = sb;
    }
}

__global__ void scan2() {
    __shared__ float bufB[NCHUNK], bufA[NCHUNK];
    int d = blockIdx.x;
    int c = threadIdx.x;
    float origB = g_chunkB[c * 65 + d];
    float origA = g_chunkA[c * 65 + d];
    bufB[c] = origB;
    bufA[NCHUNK - 1 - c] = origA;
    __syncthreads();
    #pragma unroll
    for (int off = 1; off < NCHUNK; off <<= 1) {
        float tb = (c >= off) ? bufB[c - off] : 0.f;
        float ta = (c >= off) ? bufA[c - off] : 0.f;
        __syncthreads();
        bufB[c] += tb;
        bufA[c] += ta;
        __syncthreads();
    }
    g_chunkB[c * 65 + d] = bufB[c] - origB;
    g_chunkA[c * 65 + d] = bufA[NCHUNK - 1 - c] - origA;
}

__global__ void scan3() {
    __shared__ float sA[64], sB[64];
    __shared__ int sI[64];
    int c = blockIdx.x, tid = threadIdx.x;
    if (tid < 64) {
        sA[tid] = g_A[c * 64 + tid];
        sB[tid] = g_B[c * 64 + tid];
        sI[tid] = g_sidx[c * 64 + tid];
    }
    __syncthreads();
    if (tid <= 64) {
        int d = tid;
        float run = g_chunkB[c * 65 + d];
        #pragma unroll 4
        for (int mq = 0; mq < 64; ++mq) {
            size_t kk = (size_t)(c * 64 + mq);
            g_preB[kk * 65 + d] = run;
            float xv = (d < 64) ? g_hlast[sI[mq] * 64 + d] : 1.f;
            run += sB[mq] * xv;
        }
        if (c == NCHUNK - 1) g_preB[(size_t)NROWS * 65 + d] = run;
        float runA = g_chunkA[c * 65 + d];
        #pragma unroll 4
        for (int mq = 63; mq >= 0; --mq) {
            float xv = (d < 64) ? g_hlast[sI[mq] * 64 + d] : 1.f;
            runA += sA[mq] * xv;
            g_suffA[(size_t)(c * 64 + mq) * 65 + d] = runA;
        }
        if (c == NCHUNK - 1) g_suffA[(size_t)NROWS * 65 + d] = 0.f;
    }
}

__global__ void __launch_bounds__(256)
final_kernel(const float* __restrict__ Wfc, const float* __restrict__ bfc,
             const float* __restrict__ Wout, const float* __restrict__ bout,
             float* __restrict__ out) {
    __shared__ float sWfcT[64 * 65];
    __shared__ float sWo[64], sBfc[64];
    __shared__ float sZ[8][64];
    int tid = threadIdx.x;
    for (int idx = tid; idx < 4096; idx += 256) {
        int cc = idx >> 6, kq = idx & 63;
        sWfcT[kq * 65 + cc] = Wfc[idx];
    }
    if (tid < 64) { sWo[tid] = Wout[tid]; sBfc[tid] = bfc[tid]; }
    __syncthreads();

    int wy = tid >> 5, l = tid & 31;
    int i = blockIdx.x * 8 + wy;
    float smax = g_s1sorted[NROWS - 1];
    float s2 = g_s2[i];
    float thr = -s2;

    int kk = 0;
    #pragma unroll
    for (int st = 4096; st > 0; st >>= 1)
        if (kk + st <= NROWS && g_s1sorted[kk + st - 1] <= thr) kk += st;

    float u = s2 + smax;
    float fA, fB;
    if (u > 0.f) { fA = 1.f;               fB = __expf(-0.99f * u); }
    else         { fA = __expf(0.99f * u); fB = 1.f; }

    const float* suff = &g_suffA[(size_t)kk * 65];
    const float* pre  = &g_preB[(size_t)kk * 65];
    float inv = __fdividef(1.f, fA * suff[64] + fB * pre[64]);
    #pragma unroll
    for (int h = 0; h < 2; ++h) {
        int d = l + h * 32;
        sZ[wy][d] = (fA * suff[d] + fB * pre[d]) * inv + g_hlast[i * 64 + d];
    }
    __syncwarp();

    float yp = 0.f;
    #pragma unroll
    for (int h = 0; h < 2; ++h) {
        int c = l + h * 32;
        float dot = sBfc[c];
        #pragma unroll 16
        for (int kq = 0; kq < 64; ++kq) dot += sZ[wy][kq] * sWfcT[kq * 65 + c];
        dot = dot > 0.f ? dot : 0.01f * dot;
        yp += dot * sWo[c];
    }
    #pragma unroll
    for (int o = 16; o; o >>= 1) yp += __shfl_xor_sync(0xffffffffu, yp, o);
    if (l == 0) out[i] = yp + bout[0];
}

// =======================================================================
extern "C" void kernel_launch(void* const* d_in, const int* in_sizes, int n_in,
                              void* d_out, int out_size) {
    const float* x    = (const float*)d_in[0];
    const float* Wih0 = (const float*)d_in[1];
    const float* Whh0 = (const float*)d_in[2];
    const float* bih0 = (const float*)d_in[3];
    const float* bhh0 = (const float*)d_in[4];
    const float* Wih1 = (const float*)d_in[5];
    const float* Whh1 = (const float*)d_in[6];
    const float* bih1 = (const float*)d_in[7];
    const float* bhh1 = (const float*)d_in[8];
    const float* Wt   = (const float*)d_in[9];
    const float* bt   = (const float*)d_in[10];
    const float* a    = (const float*)d_in[11];
    const float* Wfc  = (const float*)d_in[12];
    const float* bfc  = (const float*)d_in[13];
    const float* Wout = (const float*)d_in[14];
    const float* bout = (const float*)d_in[15];
    float* out = (float*)d_out;

    const int SM_SORT = 9216 * 8;   // padded uint64 layout
    cudaFuncSetAttribute(lstm_fused, cudaFuncAttributeMaxDynamicSharedMemorySize, SM_TOT);
    cudaFuncSetAttribute(sort_kernel, cudaFuncAttributeMaxDynamicSharedMemorySize, SM_SORT);

    lstm_fused<<<NBLK, 512, SM_TOT>>>(x, Wih0, Whh0, bih0, bhh0,
                                      Wih1, Whh1, bih1, bhh1);
    prep1<<<1, 128>>>(Wt, bt, a);
    prep2<<<NROWS / 8, 256>>>();
    sort_kernel<<<1, 1024, SM_SORT>>>();
    scan1<<<NCHUNK, 128>>>();
    scan2<<<65, NCHUNK>>>();
    scan3<<<NCHUNK, 128>>>();
    final_kernel<<<NROWS / 8, 256>>>(Wfc, bfc, Wout, bout, out);
}

// round 15
// speedup vs baseline: 1.7965x; 1.0333x over previous
#include <cuda_runtime.h>
#include <cuda_fp16.h>
#include <math.h>
#include <stdint.h>

#define NROWS 8192
#define TT    60
#define NCHUNK 128
#define NBLK  128

// -------- device scratch --------
__device__ float g_hlast[NROWS * 64];
__device__ float g_s1[NROWS];
__device__ float g_s2[NROWS];
__device__ float g_v1[64];
__device__ float g_v2[64];
__device__ float g_c12[2];
__device__ float g_s1sorted[NROWS];
__device__ int   g_sidx[NROWS];
__device__ float g_A[NROWS];
__device__ float g_B[NROWS];
__device__ float g_chunkA[NCHUNK * 65];
__device__ float g_chunkB[NCHUNK * 65];
__device__ float g_preB[(size_t)(NROWS + 1) * 65];
__device__ float g_suffA[(size_t)(NROWS + 1) * 65];

__device__ __forceinline__ float tanha(float x) {
    float r;
    asm("tanh.approx.f32 %0, %1;" : "=f"(r) : "f"(x));
    return r;
}
__device__ __forceinline__ float siga(float x) { return fmaf(tanha(0.5f * x), 0.5f, 0.5f); }

// -------- warp-MMA helpers --------
__device__ __forceinline__ uint32_t smem_u32(const void* p) {
    uint32_t a;
    asm("{ .reg .u64 t; cvta.to.shared.u64 t, %1; cvt.u32.u64 %0, t; }" : "=r"(a) : "l"(p));
    return a;
}
__device__ __forceinline__ void barg(int id) {
    asm volatile("bar.sync %0, 128;" :: "r"(id) : "memory");
}
__device__ __forceinline__ void ldsm4(uint32_t* r, uint32_t a) {
    asm volatile("ldmatrix.sync.aligned.m8n8.x4.shared.b16 {%0,%1,%2,%3}, [%4];"
                 : "=r"(r[0]), "=r"(r[1]), "=r"(r[2]), "=r"(r[3]) : "r"(a));
}
__device__ __forceinline__ void ldsm4t(uint32_t* r, uint32_t a) {
    asm volatile("ldmatrix.sync.aligned.m8n8.x4.trans.shared.b16 {%0,%1,%2,%3}, [%4];"
                 : "=r"(r[0]), "=r"(r[1]), "=r"(r[2]), "=r"(r[3]) : "r"(a));
}
__device__ __forceinline__ void mma16816(float* d, const uint32_t* a, const uint32_t* b) {
    asm volatile(
        "mma.sync.aligned.m16n8k16.row.col.f32.f16.f16.f32 "
        "{%0,%1,%2,%3}, {%4,%5,%6,%7}, {%8,%9}, {%0,%1,%2,%3};"
        : "+f"(d[0]), "+f"(d[1]), "+f"(d[2]), "+f"(d[3])
        : "r"(a[0]), "r"(a[1]), "r"(a[2]), "r"(a[3]), "r"(b[0]), "r"(b[1]));
}
__device__ __forceinline__ uint16_t f2h(float v) {
    __half h = __float2half_rn(v);
    return *(uint16_t*)&h;
}
// A tile [64 rows][128 k] fp16, 256B/row, swizzled 16B chunks
__device__ __forceinline__ uint32_t offA(int r, int k) {
    int ck = k >> 3;
    return (uint32_t)(r * 256 + (((ck & 8) | ((ck ^ r) & 7)) << 4) + (k & 7) * 2);
}
// W tile [k][256 n] fp16, 512B/row
__device__ __forceinline__ uint32_t offW(int k, int n) {
    int cn = n >> 3;
    return (uint32_t)(k * 512 + (((cn & 24) | ((cn ^ k) & 7)) << 4) + (n & 7) * 2);
}

// SMEM layout (bytes)
#define S_W0   0
#define S_W1   40960
#define S_A0   106496
#define S_A1   139264
#define S_B0   172032
#define S_B1   173056
#define SM_TOT 174080

// =======================================================================
// FUSED two-layer HMMA LSTM (identical to R13/R14-passing version)
// =======================================================================
__global__ void __launch_bounds__(512, 1)
lstm_fused(const float* __restrict__ xin,
           const float* __restrict__ Wih0, const float* __restrict__ Whh0,
           const float* __restrict__ bih0, const float* __restrict__ bhh0,
           const float* __restrict__ Wih1, const float* __restrict__ Whh1,
           const float* __restrict__ bih1, const float* __restrict__ bhh1) {
    extern __shared__ char smem[];
    const uint32_t sbase = smem_u32(smem);

    const int tid = threadIdx.x, lane = tid & 31, wid = tid >> 5;
    const int rw = wid >> 2, cg = wid & 3;
    const int t4 = lane & 3, g8 = lane >> 2;
    const int r0 = rw * 16;
    const int rowb = blockIdx.x * 64;
    const int row_st = r0 + g8 + ((t4 & 1) ? 8 : 0);
    const int m = lane >> 3, q = lane & 7;
    const int t128 = cg * 32 + lane;
    const int barid = rw + 1;

    for (int idx = tid; idx < 80 * 256; idx += 512) {
        int k = idx >> 8, n = idx & 255;
        int go = (n & 3) * 64 + (n >> 2);
        float w = (k < 64) ? Whh0[go * 64 + k]
                           : ((k - 64 < 6) ? Wih0[go * 6 + (k - 64)] : 0.f);
        *(uint16_t*)(smem + S_W0 + offW(k, n)) = f2h(w);
    }
    for (int idx = tid; idx < 128 * 256; idx += 512) {
        int k = idx >> 8, n = idx & 255;
        int go = (n & 3) * 64 + (n >> 2);
        float w = (k < 64) ? Whh1[go * 64 + k] : Wih1[go * 64 + (k - 64)];
        *(uint16_t*)(smem + S_W1 + offW(k, n)) = f2h(w);
    }
    for (int i = tid; i < 4096; i += 512) ((uint4*)(smem + S_A0))[i] = make_uint4(0, 0, 0, 0);
    if (tid < 256) {
        int go = (tid & 3) * 64 + (tid >> 2);
        ((float*)(smem + S_B0))[tid] = bih0[go] + bhh0[go];
        ((float*)(smem + S_B1))[tid] = bih1[go] + bhh1[go];
    }
    __syncthreads();

    const int xrow = r0 + t128 / 6, xd = t128 - (t128 / 6) * 6;
    float xf = 0.f;
    auto pfx = [&](int t) {
        if (t128 < 96) xf = xin[((size_t)(rowb + xrow) * TT + t) * 6 + xd];
    };
    auto stx = [&](int buf) {
        if (t128 < 96)
            *(uint16_t*)(smem + S_A0 + buf * 16384 + offA(xrow, 64 + xd)) = f2h(xf);
    };

    pfx(0);
    stx(0);
    __syncthreads();

    float c0[8], c1[8];
    #pragma unroll
    for (int nt = 0; nt < 8; ++nt) { c0[nt] = 0.f; c1[nt] = 0.f; }

    const int kb = cg * 16 + ((t4 & 2) ? 8 : 0);
    float d[8][4];

    auto mma_phase = [&](uint32_t abase, uint32_t wbase, int nch, int biasofs) {
        #pragma unroll
        for (int nt = 0; nt < 8; ++nt) {
            float2 b2 = *(const float2*)(smem + biasofs + (cg * 64 + nt * 8 + t4 * 2) * 4);
            d[nt][0] = b2.x; d[nt][1] = b2.y; d[nt][2] = b2.x; d[nt][3] = b2.y;
        }
        #pragma unroll 2
        for (int ch = 0; ch < nch; ++ch) {
            int ar = r0 + (m & 1) * 8 + q;
            int ak = ch * 16 + (m >> 1) * 8;
            uint32_t av[4];
            ldsm4(av, abase + offA(ar, ak));
            int bk = ch * 16 + (m & 1) * 8 + q;
            uint32_t bw[16];
            #pragma unroll
            for (int pp = 0; pp < 4; ++pp)
                ldsm4t(&bw[4 * pp], wbase + offW(bk, cg * 64 + (2 * pp + (m >> 1)) * 8));
            #pragma unroll
            for (int nt = 0; nt < 8; ++nt) mma16816(d[nt], av, &bw[2 * nt]);
        }
    };

    auto cell_phase = [&](float* cst, float* hf, uint4& pk) {
        uint32_t w0a[8], w1a[8];
        #pragma unroll
        for (int nt = 0; nt < 8; ++nt) {
            float e0 = __shfl_xor_sync(0xffffffffu, d[nt][0], 1);
            float e1 = __shfl_xor_sync(0xffffffffu, d[nt][1], 1);
            float e2 = __shfl_xor_sync(0xffffffffu, d[nt][2], 1);
            float e3 = __shfl_xor_sync(0xffffffffu, d[nt][3], 1);
            float iv, fv, gv, ov;
            if (t4 & 1) { iv = e2; fv = e3; gv = d[nt][2]; ov = d[nt][3]; }
            else        { iv = d[nt][0]; fv = d[nt][1]; gv = e0; ov = e1; }
            float cc = siga(fv) * cst[nt] + siga(iv) * tanha(gv);
            cst[nt] = cc;
            float hh = siga(ov) * tanha(cc);
            hf[nt] = hh;
            uint32_t hpk = (uint32_t)f2h(hh);
            uint32_t rv = __shfl_xor_sync(0xffffffffu, hpk, 2);
            w0a[nt] = (t4 & 2) ? rv : hpk;
            w1a[nt] = (t4 & 2) ? hpk : rv;
        }
        const int ntb = (t4 & 2) ? 4 : 0;
        pk = make_uint4(w0a[ntb] | (w1a[ntb] << 16),
                        w0a[ntb + 1] | (w1a[ntb + 1] << 16),
                        w0a[ntb + 2] | (w1a[ntb + 2] << 16),
                        w0a[ntb + 3] | (w1a[ntb + 3] << 16));
    };

    #pragma unroll 1
    for (int t = 0; t < TT; ++t) {
        const int p = t & 1;
        const uint32_t a0r = sbase + (uint32_t)(S_A0 + p * 16384);
        char* a0w = smem + S_A0 + (1 - p) * 16384;
        const uint32_t a1r = sbase + (uint32_t)(S_A1 + p * 16384);
        char* a1cur = smem + S_A1 + p * 16384;
        char* a1w = smem + S_A1 + (1 - p) * 16384;

        if (t < TT - 1) pfx(t + 1);

        mma_phase(a0r, sbase + S_W0, 5, S_B0);
        float hf[8];
        uint4 pk;
        cell_phase(c0, hf, pk);
        if (t < TT - 1) {
            *(uint4*)(a0w + offA(row_st, kb)) = pk;
            stx(1 - p);
        }
        *(uint4*)(a1cur + offA(row_st, 64 + kb)) = pk;
        barg(barid);

        mma_phase(a1r, sbase + S_W1, 8, S_B1);
        cell_phase(c1, hf, pk);
        if (t < TT - 1) *(uint4*)(a1w + offA(row_st, kb)) = pk;
        else {
            #pragma unroll
            for (int nt = 0; nt < 8; ++nt)
                g_hlast[(rowb + row_st) * 64 + cg * 16 + 2 * nt + (t4 >> 1)] = hf[nt];
        }
        barg(barid);
    }
}

// =======================================================================
// GAT prep
// =======================================================================
__global__ void prep1(const float* __restrict__ Wt, const float* __restrict__ bt,
                      const float* __restrict__ a) {
    int tid = threadIdx.x;
    if (tid < 64) {
        float v = 0.f;
        for (int g = 0; g < 64; ++g) v += Wt[g * 64 + tid] * a[g];
        g_v1[tid] = v;
    } else if (tid < 128) {
        int k = tid - 64;
        float v = 0.f;
        for (int g = 0; g < 64; ++g) v += Wt[g * 64 + k] * a[64 + g];
        g_v2[k] = v;
    }
    if (tid == 0) {
        float c = 0.f;
        for (int g = 0; g < 64; ++g) c += bt[g] * a[g];
        g_c12[0] = c;
    }
    if (tid == 1) {
        float c = 0.f;
        for (int g = 0; g < 64; ++g) c += bt[g] * a[64 + g];
        g_c12[1] = c;
    }
}

__global__ void prep2() {
    int lane = threadIdx.x & 31, w = threadIdx.x >> 5;
    int r = blockIdx.x * 8 + w;
    float l0 = g_hlast[r * 64 + lane], l1 = g_hlast[r * 64 + 32 + lane];
    float p1 = l0 * g_v1[lane] + l1 * g_v1[lane + 32];
    float p2 = l0 * g_v2[lane] + l1 * g_v2[lane + 32];
    #pragma unroll
    for (int o = 16; o; o >>= 1) {
        p1 += __shfl_xor_sync(0xffffffffu, p1, o);
        p2 += __shfl_xor_sync(0xffffffffu, p2, o);
    }
    if (lane == 0) {
        g_s1[r] = p1 + g_c12[0];
        g_s2[r] = p2 + g_c12[1];
    }
}

// =======================================================================
// Bitonic sort, packed u64 (key|idx). Thread owns 8 contiguous elements.
// strides 1..4: intra-thread; strides 8..128: warp shuffles (lane^(s/8));
// strides >=256: smem (padded phys(i)=i+(i>>3)). Only 15 smem stages.
// =======================================================================
__device__ __forceinline__ int sphys(int i) { return i + (i >> 3); }

__global__ void __launch_bounds__(1024, 1) sort_kernel() {
    extern __shared__ unsigned long long sv[];
    const int tid = threadIdx.x;
    const int lane = tid & 31;
    for (int i = tid; i < NROWS; i += 1024) {
        uint32_t u = __float_as_uint(g_s1[i]);
        u = (u & 0x80000000u) ? ~u : (u | 0x80000000u);
        sv[sphys(i)] = ((unsigned long long)u << 32) | (uint32_t)i;
    }
    __syncthreads();

    unsigned long long r[8];
    auto lda = [&]() {
        #pragma unroll
        for (int e = 0; e < 8; ++e) r[e] = sv[tid * 9 + e];
    };
    auto sta = [&]() {
        #pragma unroll
        for (int e = 0; e < 8; ++e) sv[tid * 9 + e] = r[e];
    };
    auto cas = [&](int a, int b, bool up) {
        if ((r[a] > r[b]) == up) { unsigned long long t = r[a]; r[a] = r[b]; r[b] = t; }
    };
    auto intra = [&](bool up) {  // strides 4,2,1
        cas(0, 4, up); cas(1, 5, up); cas(2, 6, up); cas(3, 7, up);
        cas(0, 2, up); cas(1, 3, up); cas(4, 6, up); cas(5, 7, up);
        cas(0, 1, up); cas(2, 3, up); cas(4, 5, up); cas(6, 7, up);
    };
    auto shufstage = [&](int sh, bool up) {  // stride = sh*8, partner lane^sh
        bool keepMin = (up == ((lane & sh) == 0));
        #pragma unroll
        for (int e = 0; e < 8; ++e) {
            unsigned long long o = __shfl_xor_sync(0xffffffffu, r[e], sh);
            r[e] = keepMin ? (r[e] < o ? r[e] : o) : (r[e] > o ? r[e] : o);
        }
    };

    // sizes 2..8 intra-thread
    lda();
    cas(0, 1, true);  cas(2, 3, false); cas(4, 5, true);  cas(6, 7, false);
    cas(0, 2, true);  cas(1, 3, true);  cas(4, 6, false); cas(5, 7, false);
    cas(0, 1, true);  cas(2, 3, true);  cas(4, 5, false); cas(6, 7, false);
    {
        bool up8 = (tid & 1) == 0;
        intra(up8);
    }
    // sizes 16..256 fully in registers/shuffles (no barriers)
    #pragma unroll
    for (int size = 16; size <= 256; size <<= 1) {
        bool up = (tid & (size >> 3)) == 0;
        for (int sh = size >> 4; sh >= 1; sh >>= 1) shufstage(sh, up);
        intra(up);
    }
    sta();

    // sizes 512..8192: smem for strides >=256, then registers
    for (int size = 512; size <= NROWS; size <<= 1) {
        for (int stride = size >> 1; stride >= 256; stride >>= 1) {
            __syncthreads();
            #pragma unroll
            for (int e = 0; e < 4; ++e) {
                int p = e * 1024 + tid;
                int i = ((p & ~(stride - 1)) << 1) | (p & (stride - 1));
                int j = i + stride;
                bool up = (i & size) == 0;
                unsigned long long vi = sv[sphys(i)], vj = sv[sphys(j)];
                if ((vi > vj) == up) { sv[sphys(i)] = vj; sv[sphys(j)] = vi; }
            }
        }
        __syncthreads();
        lda();
        bool up = (tid & (size >> 3)) == 0;
        #pragma unroll
        for (int sh = 16; sh >= 1; sh >>= 1) shufstage(sh, up);
        intra(up);
        sta();
    }
    __syncthreads();

    for (int i = tid; i < NROWS; i += 1024) {
        unsigned long long v = sv[sphys(i)];
        uint32_t u = (uint32_t)(v >> 32);
        uint32_t fb = (u & 0x80000000u) ? (u & 0x7FFFFFFFu) : ~u;
        g_s1sorted[i] = __uint_as_float(fb);
        g_sidx[i] = (int)(v & 0xFFFFFFFFu);
    }
}

__global__ void scan1() {
    __shared__ float sA[64], sB[64];
    __shared__ int sI[64];
    int c = blockIdx.x, tid = threadIdx.x;
    if (tid < 64) {
        float smax = g_s1sorted[NROWS - 1];
        float key = g_s1sorted[c * 64 + tid];
        float A = __expf(key - smax);
        float B = __expf(0.01f * (key - smax));
        sA[tid] = A; sB[tid] = B;
        sI[tid] = g_sidx[c * 64 + tid];
        g_A[c * 64 + tid] = A;
        g_B[c * 64 + tid] = B;
    }
    __syncthreads();
    if (tid <= 64) {
        float sa = 0.f, sb = 0.f;
        #pragma unroll 4
        for (int mq = 0; mq < 64; ++mq) {
            float xv = (tid < 64) ? g_hlast[sI[mq] * 64 + tid] : 1.f;
            sa += sA[mq] * xv;
            sb += sB[mq] * xv;
        }
        g_chunkA[c * 65 + tid] = sa;
        g_chunkB[c * 65 + tid] = sb;
    }
}

__global__ void scan2() {
    __shared__ float bufB[NCHUNK], bufA[NCHUNK];
    int d = blockIdx.x;
    int c = threadIdx.x;
    float origB = g_chunkB[c * 65 + d];
    float origA = g_chunkA[c * 65 + d];
    bufB[c] = origB;
    bufA[NCHUNK - 1 - c] = origA;
    __syncthreads();
    #pragma unroll
    for (int off = 1; off < NCHUNK; off <<= 1) {
        float tb = (c >= off) ? bufB[c - off] : 0.f;
        float ta = (c >= off) ? bufA[c - off] : 0.f;
        __syncthreads();
        bufB[c] += tb;
        bufA[c] += ta;
        __syncthreads();
    }
    g_chunkB[c * 65 + d] = bufB[c] - origB;
    g_chunkA[c * 65 + d] = bufA[NCHUNK - 1 - c] - origA;
}

__global__ void scan3() {
    __shared__ float sA[64], sB[64];
    __shared__ int sI[64];
    int c = blockIdx.x, tid = threadIdx.x;
    if (tid < 64) {
        sA[tid] = g_A[c * 64 + tid];
        sB[tid] = g_B[c * 64 + tid];
        sI[tid] = g_sidx[c * 64 + tid];
    }
    __syncthreads();
    if (tid <= 64) {
        int d = tid;
        float run = g_chunkB[c * 65 + d];
        #pragma unroll 4
        for (int mq = 0; mq < 64; ++mq) {
            size_t kk = (size_t)(c * 64 + mq);
            g_preB[kk * 65 + d] = run;
            float xv = (d < 64) ? g_hlast[sI[mq] * 64 + d] : 1.f;
            run += sB[mq] * xv;
        }
        if (c == NCHUNK - 1) g_preB[(size_t)NROWS * 65 + d] = run;
        float runA = g_chunkA[c * 65 + d];
        #pragma unroll 4
        for (int mq = 63; mq >= 0; --mq) {
            float xv = (d < 64) ? g_hlast[sI[mq] * 64 + d] : 1.f;
            runA += sA[mq] * xv;
            g_suffA[(size_t)(c * 64 + mq) * 65 + d] = runA;
        }
        if (c == NCHUNK - 1) g_suffA[(size_t)NROWS * 65 + d] = 0.f;
    }
}

__global__ void __launch_bounds__(256)
final_kernel(const float* __restrict__ Wfc, const float* __restrict__ bfc,
             const float* __restrict__ Wout, const float* __restrict__ bout,
             float* __restrict__ out) {
    __shared__ float sWfcT[64 * 65];
    __shared__ float sWo[64], sBfc[64];
    __shared__ float sZ[8][64];
    int tid = threadIdx.x;
    for (int idx = tid; idx < 4096; idx += 256) {
        int cc = idx >> 6, kq = idx & 63;
        sWfcT[kq * 65 + cc] = Wfc[idx];
    }
    if (tid < 64) { sWo[tid] = Wout[tid]; sBfc[tid] = bfc[tid]; }
    __syncthreads();

    int wy = tid >> 5, l = tid & 31;
    int i = blockIdx.x * 8 + wy;
    float smax = g_s1sorted[NROWS - 1];
    float s2 = g_s2[i];
    float thr = -s2;

    int kk = 0;
    #pragma unroll
    for (int st = 4096; st > 0; st >>= 1)
        if (kk + st <= NROWS && g_s1sorted[kk + st - 1] <= thr) kk += st;

    float u = s2 + smax;
    float fA, fB;
    if (u > 0.f) { fA = 1.f;               fB = __expf(-0.99f * u); }
    else         { fA = __expf(0.99f * u); fB = 1.f; }

    const float* suff = &g_suffA[(size_t)kk * 65];
    const float* pre  = &g_preB[(size_t)kk * 65];
    float inv = __fdividef(1.f, fA * suff[64] + fB * pre[64]);
    #pragma unroll
    for (int h = 0; h < 2; ++h) {
        int d = l + h * 32;
        sZ[wy][d] = (fA * suff[d] + fB * pre[d]) * inv + g_hlast[i * 64 + d];
    }
    __syncwarp();

    float yp = 0.f;
    #pragma unroll
    for (int h = 0; h < 2; ++h) {
        int c = l + h * 32;
        float dot = sBfc[c];
        #pragma unroll 16
        for (int kq = 0; kq < 64; ++kq) dot += sZ[wy][kq] * sWfcT[kq * 65 + c];
        dot = dot > 0.f ? dot : 0.01f * dot;
        yp += dot * sWo[c];
    }
    #pragma unroll
    for (int o = 16; o; o >>= 1) yp += __shfl_xor_sync(0xffffffffu, yp, o);
    if (l == 0) out[i] = yp + bout[0];
}

// =======================================================================
extern "C" void kernel_launch(void* const* d_in, const int* in_sizes, int n_in,
                              void* d_out, int out_size) {
    const float* x    = (const float*)d_in[0];
    const float* Wih0 = (const float*)d_in[1];
    const float* Whh0 = (const float*)d_in[2];
    const float* bih0 = (const float*)d_in[3];
    const float* bhh0 = (const float*)d_in[4];
    const float* Wih1 = (const float*)d_in[5];
    const float* Whh1 = (const float*)d_in[6];
    const float* bih1 = (const float*)d_in[7];
    const float* bhh1 = (const float*)d_in[8];
    const float* Wt   = (const float*)d_in[9];
    const float* bt   = (const float*)d_in[10];
    const float* a    = (const float*)d_in[11];
    const float* Wfc  = (const float*)d_in[12];
    const float* bfc  = (const float*)d_in[13];
    const float* Wout = (const float*)d_in[14];
    const float* bout = (const float*)d_in[15];
    float* out = (float*)d_out;

    const int SM_SORT = 9216 * 8;
    cudaFuncSetAttribute(lstm_fused, cudaFuncAttributeMaxDynamicSharedMemorySize, SM_TOT);
    cudaFuncSetAttribute(sort_kernel, cudaFuncAttributeMaxDynamicSharedMemorySize, SM_SORT);

    lstm_fused<<<NBLK, 512, SM_TOT>>>(x, Wih0, Whh0, bih0, bhh0,
                                      Wih1, Whh1, bih1, bhh1);
    prep1<<<1, 128>>>(Wt, bt, a);
    prep2<<<NROWS / 8, 256>>>();
    sort_kernel<<<1, 1024, SM_SORT>>>();
    scan1<<<NCHUNK, 128>>>();
    scan2<<<65, NCHUNK>>>();
    scan3<<<NCHUNK, 128>>>();
    final_kernel<<<NROWS / 8, 256>>>(Wfc, bfc, Wout, bout, out);
}